// round 1
// baseline (speedup 1.0000x reference)
#include <cuda_runtime.h>
#include <cuda_bf16.h>
#include <math.h>

// ---------------- problem constants ----------------
#define BB 8
#define TT 64
#define EE 128
#define CC 256
#define HH2 512          // conv hidden
#define MM 1024          // mlp hidden
#define NHEAD 8
#define DD 32
#define RROWS 65536      // B*T*E
#define LNEPS 1e-5f

// ---------------- device scratch (allocation-free rule: __device__ globals) ----
__device__ __align__(128) float g_xs [RROWS * CC];   // xs / xt / xm
__device__ __align__(128) float g_q  [RROWS * CC];   // q / proj-out
__device__ __align__(128) float g_k  [RROWS * CC];   // k / x1
__device__ __align__(128) float g_v  [RROWS * CC];   // v / x2
__device__ __align__(128) float g_o  [RROWS * CC];   // attention out
__device__ __align__(128) float g_y1 [RROWS * HH2];  // conv1 out
__device__ __align__(128) float g_big[RROWS * MM];   // mlp hidden
__device__ __align__(128) float g_w1t[768 * 512];    // conv1 weight transposed [kk][h], kk=j*256+c
__device__ __align__(128) float g_w2t[512 * 256];    // conv2 weight transposed [h][c]
__device__ __align__(128) float g_maskf[EE * EE];    // 0.5 * adj_mask
__device__ __align__(128) float g_bn1s[HH2], g_bn1b[HH2], g_bn2s[CC], g_bn2b[CC];

// ---------------- prep: transposes + BN folding + mask scaling ----------------
__global__ void prep_kernel(const float* __restrict__ w1, const float* __restrict__ w2,
                            const int* __restrict__ mask,
                            const float* __restrict__ b1w, const float* __restrict__ b1b,
                            const float* __restrict__ b1m, const float* __restrict__ b1v,
                            const float* __restrict__ b2w, const float* __restrict__ b2b,
                            const float* __restrict__ b2m, const float* __restrict__ b2v)
{
    int idx = blockIdx.x * blockDim.x + threadIdx.x;
    if (idx < 768 * 512) {
        int kk = idx >> 9, h = idx & 511;
        int j = kk >> 8, c = kk & 255;
        g_w1t[idx] = w1[h * 768 + c * 3 + j];
    }
    if (idx < 512 * 256) {
        int h = idx >> 8, c = idx & 255;
        g_w2t[idx] = w2[c * 512 + h];
    }
    if (idx < EE * EE) g_maskf[idx] = 0.5f * (float)mask[idx];
    if (idx < HH2) {
        float s = b1w[idx] * rsqrtf(b1v[idx] + LNEPS);
        g_bn1s[idx] = s;
        g_bn1b[idx] = b1b[idx] - b1m[idx] * s;
    }
    if (idx < CC) {
        float s = b2w[idx] * rsqrtf(b2v[idx] + LNEPS);
        g_bn2s[idx] = s;
        g_bn2b[idx] = b2b[idx] - b2m[idx] * s;
    }
}

// ---------------- LayerNorm over C=256, one block per row ----------------
__global__ void ln_kernel(const float* __restrict__ in, const float* __restrict__ w,
                          const float* __restrict__ b, float* __restrict__ out)
{
    int row = blockIdx.x;
    int tid = threadIdx.x;
    size_t idx = (size_t)row * CC + tid;
    float v = in[idx];
    float s = v, s2 = v * v;
    #pragma unroll
    for (int o = 16; o; o >>= 1) {
        s  += __shfl_down_sync(0xffffffffu, s,  o);
        s2 += __shfl_down_sync(0xffffffffu, s2, o);
    }
    __shared__ float sa[8], sb[8];
    int lane = tid & 31, wid = tid >> 5;
    if (!lane) { sa[wid] = s; sb[wid] = s2; }
    __syncthreads();
    if (tid < 32) {
        s  = (tid < 8) ? sa[tid] : 0.f;
        s2 = (tid < 8) ? sb[tid] : 0.f;
        #pragma unroll
        for (int o = 4; o; o >>= 1) {
            s  += __shfl_down_sync(0xffffffffu, s,  o);
            s2 += __shfl_down_sync(0xffffffffu, s2, o);
        }
        if (!tid) {
            float mean = s * (1.f / CC);
            float var  = s2 * (1.f / CC) - mean * mean;
            sa[0] = mean;
            sb[0] = rsqrtf(var + LNEPS);
        }
    }
    __syncthreads();
    out[idx] = (v - sa[0]) * sb[0] * w[tid] + b[tid];
}

// --------- fused: LN(P) with on_w/on_b, then x1 = x + xs + gamma_s*LN ----------
__global__ void lnres_kernel(const float* __restrict__ P, const float* __restrict__ x,
                             const float* __restrict__ xs, const float* __restrict__ w,
                             const float* __restrict__ b, const float* __restrict__ gamma,
                             float* __restrict__ out)
{
    int row = blockIdx.x;
    int tid = threadIdx.x;
    size_t idx = (size_t)row * CC + tid;
    float v = P[idx];
    float s = v, s2 = v * v;
    #pragma unroll
    for (int o = 16; o; o >>= 1) {
        s  += __shfl_down_sync(0xffffffffu, s,  o);
        s2 += __shfl_down_sync(0xffffffffu, s2, o);
    }
    __shared__ float sa[8], sb[8];
    int lane = tid & 31, wid = tid >> 5;
    if (!lane) { sa[wid] = s; sb[wid] = s2; }
    __syncthreads();
    if (tid < 32) {
        s  = (tid < 8) ? sa[tid] : 0.f;
        s2 = (tid < 8) ? sb[tid] : 0.f;
        #pragma unroll
        for (int o = 4; o; o >>= 1) {
            s  += __shfl_down_sync(0xffffffffu, s,  o);
            s2 += __shfl_down_sync(0xffffffffu, s2, o);
        }
        if (!tid) {
            float mean = s * (1.f / CC);
            float var  = s2 * (1.f / CC) - mean * mean;
            sa[0] = mean;
            sb[0] = rsqrtf(var + LNEPS);
        }
    }
    __syncthreads();
    float ln = (v - sa[0]) * sb[0] * w[tid] + b[tid];
    out[idx] = x[idx] + xs[idx] + gamma[0] * ln;
}

// ---------------- attention per (b,t,head): E=128, D=32, no softmax ------------
__global__ void attn_kernel(const float* __restrict__ Q, const float* __restrict__ K,
                            const float* __restrict__ V, float* __restrict__ O)
{
    __shared__ float4 Ks[1024];
    __shared__ float4 Vs[1024];
    int h  = blockIdx.x & 7;
    int bt = blockIdx.x >> 3;
    int tid = threadIdx.x;          // 0..127 == e
    size_t base = (size_t)bt * EE * CC + h * DD;
    for (int idx = tid; idx < 1024; idx += 128) {
        int f = idx >> 3, i = idx & 7;
        Ks[idx] = *(const float4*)&K[base + (size_t)f * CC + i * 4];
        Vs[idx] = *(const float4*)&V[base + (size_t)f * CC + i * 4];
    }
    float4 q[8], o[8];
    #pragma unroll
    for (int i = 0; i < 8; i++) {
        q[i] = *(const float4*)&Q[base + (size_t)tid * CC + i * 4];
        o[i] = make_float4(0.f, 0.f, 0.f, 0.f);
    }
    __syncthreads();
    const float* mrow = g_maskf + tid * EE;
    for (int f = 0; f < EE; f++) {
        float s = 0.f;
        #pragma unroll
        for (int i = 0; i < 8; i++) {
            float4 k4 = Ks[f * 8 + i];
            s += q[i].x * k4.x + q[i].y * k4.y + q[i].z * k4.z + q[i].w * k4.w;
        }
        float wgt = s * mrow[f] + 0.5f;     // (attn*mask + 1)*0.5
        #pragma unroll
        for (int i = 0; i < 8; i++) {
            float4 v4 = Vs[f * 8 + i];
            o[i].x += wgt * v4.x; o[i].y += wgt * v4.y;
            o[i].z += wgt * v4.z; o[i].w += wgt * v4.w;
        }
    }
    #pragma unroll
    for (int i = 0; i < 8; i++)
        *(float4*)&O[base + (size_t)tid * CC + i * 4] = o[i];
}

// ---------------- generic tiled SGEMM 64x64x16, flexible epilogue --------------
// C = A[M,K] @ B[K,N] row-major.  Epilogue:
//   if colScale: v = v*colScale[col] + colShift[col]   else if colShift: v += colShift[col]
//   if doGelu:   v = gelu_exact(v)
//   if res:      v = resCoef*res[idx] + (*vMul or 1)*v
__device__ __forceinline__ float gelu_exact(float v)
{
    return 0.5f * v * (1.f + erff(v * 0.70710678118654752f));
}

__global__ void gemm_kernel(const float* __restrict__ A, const float* __restrict__ B,
                            float* __restrict__ C, int M, int N, int K,
                            const float* __restrict__ colScale,
                            const float* __restrict__ colShift,
                            int doGelu,
                            const float* __restrict__ res, float resCoef,
                            const float* __restrict__ vMul)
{
    __shared__ __align__(16) float As[16][64];
    __shared__ __align__(16) float Bs[16][64];
    int tid = threadIdx.x;
    int m0 = blockIdx.y * 64, n0 = blockIdx.x * 64;
    int arow = tid >> 2,  ak   = (tid & 3) << 2;
    int bk   = tid >> 4,  bcol = (tid & 15) << 2;
    int ty   = tid >> 4,  tx   = tid & 15;
    const float* Arow = A + (size_t)(m0 + arow) * K;
    float acc[4][4] = {};
    for (int k0 = 0; k0 < K; k0 += 16) {
        float4 av = *(const float4*)&Arow[k0 + ak];
        As[ak + 0][arow] = av.x; As[ak + 1][arow] = av.y;
        As[ak + 2][arow] = av.z; As[ak + 3][arow] = av.w;
        *(float4*)&Bs[bk][bcol] = *(const float4*)&B[(size_t)(k0 + bk) * N + n0 + bcol];
        __syncthreads();
        #pragma unroll
        for (int k = 0; k < 16; k++) {
            float4 a = *(const float4*)&As[k][ty << 2];
            float4 b = *(const float4*)&Bs[k][tx << 2];
            float av_[4] = {a.x, a.y, a.z, a.w};
            float bv_[4] = {b.x, b.y, b.z, b.w};
            #pragma unroll
            for (int i = 0; i < 4; i++)
                #pragma unroll
                for (int j = 0; j < 4; j++)
                    acc[i][j] += av_[i] * bv_[j];
        }
        __syncthreads();
    }
    float vm = vMul ? *vMul : 1.0f;
    #pragma unroll
    for (int i = 0; i < 4; i++) {
        int row = m0 + (ty << 2) + i;
        #pragma unroll
        for (int j = 0; j < 4; j++) {
            int col = n0 + (tx << 2) + j;
            size_t idx = (size_t)row * N + col;
            float v = acc[i][j];
            if (colScale)      v = v * colScale[col] + colShift[col];
            else if (colShift) v = v + colShift[col];
            if (doGelu)        v = gelu_exact(v);
            if (res)           v = resCoef * res[idx] + vm * v;
            C[idx] = v;
        }
    }
}

// -------- conv1 as GEMM with gathered A: rows r=(b,t,e), kk=j*256+c, t-pad ------
__global__ void gemm_conv1_kernel(const float* __restrict__ XT, float* __restrict__ C)
{
    const int N = HH2, K = 768;
    __shared__ __align__(16) float As[16][64];
    __shared__ __align__(16) float Bs[16][64];
    int tid = threadIdx.x;
    int m0 = blockIdx.y * 64, n0 = blockIdx.x * 64;
    int arow = tid >> 2,  ak   = (tid & 3) << 2;
    int bk   = tid >> 4,  bcol = (tid & 15) << 2;
    int ty   = tid >> 4,  tx   = tid & 15;
    int r = m0 + arow;
    int t = (r >> 7) & 63;            // r = (b*T+t)*E + e ; E=128, T=64
    float acc[4][4] = {};
    for (int k0 = 0; k0 < K; k0 += 16) {
        int kk = k0 + ak;
        int j  = kk >> 8;             // 0,1,2  (constant across the float4)
        int c  = kk & 255;
        int tt = t + j - 1;
        float4 av = make_float4(0.f, 0.f, 0.f, 0.f);
        if ((unsigned)tt < 64u)
            av = *(const float4*)&XT[((size_t)r + (size_t)(j - 1) * EE) * CC + c];
        As[ak + 0][arow] = av.x; As[ak + 1][arow] = av.y;
        As[ak + 2][arow] = av.z; As[ak + 3][arow] = av.w;
        *(float4*)&Bs[bk][bcol] = *(const float4*)&g_w1t[(size_t)(k0 + bk) * N + n0 + bcol];
        __syncthreads();
        #pragma unroll
        for (int k = 0; k < 16; k++) {
            float4 a = *(const float4*)&As[k][ty << 2];
            float4 b = *(const float4*)&Bs[k][tx << 2];
            float av_[4] = {a.x, a.y, a.z, a.w};
            float bv_[4] = {b.x, b.y, b.z, b.w};
            #pragma unroll
            for (int i = 0; i < 4; i++)
                #pragma unroll
                for (int jj = 0; jj < 4; jj++)
                    acc[i][jj] += av_[i] * bv_[jj];
        }
        __syncthreads();
    }
    #pragma unroll
    for (int i = 0; i < 4; i++) {
        int row = m0 + (ty << 2) + i;
        #pragma unroll
        for (int jj = 0; jj < 4; jj++) {
            int col = n0 + (tx << 2) + jj;
            float v = acc[i][jj] * g_bn1s[col] + g_bn1b[col];
            C[(size_t)row * N + col] = gelu_exact(v);
        }
    }
}

// -------------------------------- launcher --------------------------------
static float* symaddr(const void* sym)
{
    void* p = nullptr;
    cudaGetSymbolAddress(&p, sym);
    return (float*)p;
}

extern "C" void kernel_launch(void* const* d_in, const int* in_sizes, int n_in,
                              void* d_out, int out_size)
{
    const float* x       = (const float*)d_in[0];
    const int*   adj     = (const int*)  d_in[1];
    const float* n1_w    = (const float*)d_in[2];
    const float* n1_b    = (const float*)d_in[3];
    const float* q_w     = (const float*)d_in[4];
    const float* k_w     = (const float*)d_in[5];
    const float* v_w     = (const float*)d_in[6];
    const float* proj_w  = (const float*)d_in[7];
    const float* proj_b  = (const float*)d_in[8];
    const float* on_w    = (const float*)d_in[9];
    const float* on_b    = (const float*)d_in[10];
    const float* gamma_s = (const float*)d_in[11];
    const float* conv1_w = (const float*)d_in[12];
    const float* bn1_w   = (const float*)d_in[13];
    const float* bn1_b   = (const float*)d_in[14];
    const float* bn1_m   = (const float*)d_in[15];
    const float* bn1_v   = (const float*)d_in[16];
    const float* conv2_w = (const float*)d_in[17];
    const float* bn2_w   = (const float*)d_in[18];
    const float* bn2_b   = (const float*)d_in[19];
    const float* bn2_m   = (const float*)d_in[20];
    const float* bn2_v   = (const float*)d_in[21];
    const float* tn_w    = (const float*)d_in[22];
    const float* tn_b    = (const float*)d_in[23];
    const float* gamma_t = (const float*)d_in[24];
    const float* n3_w    = (const float*)d_in[25];
    const float* n3_b    = (const float*)d_in[26];
    const float* fc1_w   = (const float*)d_in[27];
    const float* fc1_b   = (const float*)d_in[28];
    const float* fc2_w   = (const float*)d_in[29];
    const float* fc2_b   = (const float*)d_in[30];
    float* out = (float*)d_out;

    float* xs  = symaddr(g_xs);
    float* q   = symaddr(g_q);
    float* k   = symaddr(g_k);
    float* v   = symaddr(g_v);
    float* o   = symaddr(g_o);
    float* y1  = symaddr(g_y1);
    float* big = symaddr(g_big);
    float* w2t = symaddr(g_w2t);
    float* bn2s = symaddr(g_bn2s);
    float* bn2b = symaddr(g_bn2b);

    // 0) prep: weight transposes, BN folding, mask scaling
    prep_kernel<<<1536, 256>>>(conv1_w, conv2_w, adj,
                               bn1_w, bn1_b, bn1_m, bn1_v,
                               bn2_w, bn2_b, bn2_m, bn2_v);

    // 1) xs = LN(x)
    ln_kernel<<<RROWS, 256>>>(x, n1_w, n1_b, xs);

    // 2) q/k/v GEMMs
    gemm_kernel<<<dim3(4, 1024), 256>>>(xs, q_w, q, RROWS, CC, CC,
                                        nullptr, nullptr, 0, nullptr, 0.f, nullptr);
    gemm_kernel<<<dim3(4, 1024), 256>>>(xs, k_w, k, RROWS, CC, CC,
                                        nullptr, nullptr, 0, nullptr, 0.f, nullptr);
    gemm_kernel<<<dim3(4, 1024), 256>>>(xs, v_w, v, RROWS, CC, CC,
                                        nullptr, nullptr, 0, nullptr, 0.f, nullptr);

    // 3) masked attention (no softmax)
    attn_kernel<<<BB * TT * NHEAD, 128>>>(q, k, v, o);

    // 4) proj: P = o @ proj_w + proj_b   (into g_q, now dead)
    gemm_kernel<<<dim3(4, 1024), 256>>>(o, proj_w, q, RROWS, CC, CC,
                                        nullptr, proj_b, 0, nullptr, 0.f, nullptr);

    // 5) x1 = x + xs + gamma_s*LN(P)   (into g_k, now dead)
    lnres_kernel<<<RROWS, 256>>>(q, x, xs, on_w, on_b, gamma_s, k);

    // 6) xt = LN(x1)   (into g_xs, now dead)
    ln_kernel<<<RROWS, 256>>>(k, tn_w, tn_b, xs);

    // 7) conv1 (gathered GEMM) + BN1 + GELU -> y1 [R,512]
    gemm_conv1_kernel<<<dim3(8, 1024), 256>>>(xs, y1);

    // 8) conv2 GEMM + BN2, then x2 = 2*x1 + gamma_t*y   (into g_v, now dead)
    gemm_kernel<<<dim3(4, 1024), 256>>>(y1, w2t, v, RROWS, CC, HH2,
                                        bn2s, bn2b, 0, k, 2.0f, gamma_t);

    // 9) xm = LN(x2)   (into g_xs)
    ln_kernel<<<RROWS, 256>>>(v, n3_w, n3_b, xs);

    // 10) fc1 + bias + GELU -> big [R,1024]
    gemm_kernel<<<dim3(16, 1024), 256>>>(xs, fc1_w, big, RROWS, MM, CC,
                                         nullptr, fc1_b, 1, nullptr, 0.f, nullptr);

    // 11) fc2 + bias + residual x2 -> out
    gemm_kernel<<<dim3(4, 1024), 256>>>(big, fc2_w, out, RROWS, CC, MM,
                                        nullptr, fc2_b, 0, v, 1.0f, nullptr);
}

// round 3
// speedup vs baseline: 2.0652x; 2.0652x over previous
#include <cuda_runtime.h>
#include <cstdint>
#include <math.h>

// ---------------- problem constants ----------------
#define BB 8
#define TT 64
#define EE 128
#define CC 256
#define HH2 512          // conv hidden
#define MM 1024          // mlp hidden
#define NHEAD 8
#define RROWS 65536      // B*T*E
#define LNEPS 1e-5f

// ---------------- device scratch (allocation-free rule) ----------------
__device__ __align__(128) float g_xs [RROWS * CC];   // xs / xt / xm
__device__ __align__(128) float g_q  [RROWS * CC];   // q / proj-out
__device__ __align__(128) float g_k  [RROWS * CC];   // k / x1
__device__ __align__(128) float g_v  [RROWS * CC];   // v / x2
__device__ __align__(128) float g_o  [RROWS * CC];   // attention out
__device__ __align__(128) float g_y1 [RROWS * HH2];  // conv1 out
__device__ __align__(128) float g_big[RROWS * MM];   // mlp hidden
// transposed weights, all [N][K] K-major (B operand, used as col-major in mma)
__device__ __align__(128) float g_bq [CC * CC];
__device__ __align__(128) float g_bk [CC * CC];
__device__ __align__(128) float g_bv [CC * CC];
__device__ __align__(128) float g_bp [CC * CC];
__device__ __align__(128) float g_bw1[HH2 * 768];    // conv1: [h][kk], kk=j*256+c
__device__ __align__(128) float g_bf1[MM * CC];
__device__ __align__(128) float g_bf2[CC * MM];
__device__ __align__(128) float g_maskf[EE * EE];    // 0.5 * adj_mask
__device__ __align__(128) float g_bn1s[HH2], g_bn1b[HH2], g_bn2s[CC], g_bn2b[CC];

// ---------------- small helpers ----------------
__device__ __forceinline__ uint32_t f2tf32(float f)
{
    uint32_t r;
    asm("cvt.rna.tf32.f32 %0, %1;" : "=r"(r) : "f"(f));
    return r;
}

__device__ __forceinline__ void mma8(float* d, const uint4& a, const uint2& b)
{
    asm volatile("mma.sync.aligned.m16n8k8.row.col.f32.tf32.tf32.f32 "
                 "{%0,%1,%2,%3}, {%4,%5,%6,%7}, {%8,%9}, {%0,%1,%2,%3};"
                 : "+f"(d[0]), "+f"(d[1]), "+f"(d[2]), "+f"(d[3])
                 : "r"(a.x), "r"(a.y), "r"(a.z), "r"(a.w), "r"(b.x), "r"(b.y));
}

__device__ __forceinline__ float gelu_exact(float v)
{
    return 0.5f * v * (1.f + erff(v * 0.70710678118654752f));
}

// ---------------- prep: weight transposes + BN folding + mask ----------------
__global__ void prep_kernel(const float* __restrict__ qw, const float* __restrict__ kw,
                            const float* __restrict__ vw, const float* __restrict__ pw,
                            const float* __restrict__ w1, const float* __restrict__ f1,
                            const float* __restrict__ f2, const int* __restrict__ mask,
                            const float* __restrict__ b1w, const float* __restrict__ b1b,
                            const float* __restrict__ b1m, const float* __restrict__ b1v,
                            const float* __restrict__ b2w, const float* __restrict__ b2b,
                            const float* __restrict__ b2m, const float* __restrict__ b2v)
{
    int idx = blockIdx.x * blockDim.x + threadIdx.x;
    if (idx < CC * CC) {
        int n = idx >> 8, k = idx & 255;
        g_bq[idx] = qw[k * CC + n];
        g_bk[idx] = kw[k * CC + n];
        g_bv[idx] = vw[k * CC + n];
        g_bp[idx] = pw[k * CC + n];
    }
    if (idx < HH2 * 768) {        // [h][kk], kk = j*256+c
        int h = idx / 768, kk = idx % 768;
        int j = kk >> 8, c = kk & 255;
        g_bw1[idx] = w1[h * 768 + c * 3 + j];
    }
    if (idx < MM * CC) {          // [n][k], n<1024
        int n = idx >> 8, k = idx & 255;
        g_bf1[idx] = f1[k * MM + n];
    }
    if (idx < CC * MM) {          // [n][k], n<256, k<1024
        int n = idx >> 10, k = idx & 1023;
        g_bf2[idx] = f2[k * CC + n];
    }
    if (idx < EE * EE) g_maskf[idx] = 0.5f * (float)mask[idx];
    if (idx < HH2) {
        float s = b1w[idx] * rsqrtf(b1v[idx] + LNEPS);
        g_bn1s[idx] = s;
        g_bn1b[idx] = b1b[idx] - b1m[idx] * s;
    }
    if (idx < CC) {
        float s = b2w[idx] * rsqrtf(b2v[idx] + LNEPS);
        g_bn2s[idx] = s;
        g_bn2b[idx] = b2b[idx] - b2m[idx] * s;
    }
}

// ---------------- LayerNorm over C=256, one block per row ----------------
__global__ void ln_kernel(const float* __restrict__ in, const float* __restrict__ w,
                          const float* __restrict__ b, float* __restrict__ out)
{
    int row = blockIdx.x;
    int tid = threadIdx.x;
    size_t idx = (size_t)row * CC + tid;
    float v = in[idx];
    float s = v, s2 = v * v;
    #pragma unroll
    for (int o = 16; o; o >>= 1) {
        s  += __shfl_down_sync(0xffffffffu, s,  o);
        s2 += __shfl_down_sync(0xffffffffu, s2, o);
    }
    __shared__ float sa[8], sb[8];
    int lane = tid & 31, wid = tid >> 5;
    if (!lane) { sa[wid] = s; sb[wid] = s2; }
    __syncthreads();
    if (tid < 32) {
        s  = (tid < 8) ? sa[tid] : 0.f;
        s2 = (tid < 8) ? sb[tid] : 0.f;
        #pragma unroll
        for (int o = 4; o; o >>= 1) {
            s  += __shfl_down_sync(0xffffffffu, s,  o);
            s2 += __shfl_down_sync(0xffffffffu, s2, o);
        }
        if (!tid) {
            float mean = s * (1.f / CC);
            float var  = s2 * (1.f / CC) - mean * mean;
            sa[0] = mean;
            sb[0] = rsqrtf(var + LNEPS);
        }
    }
    __syncthreads();
    out[idx] = (v - sa[0]) * sb[0] * w[tid] + b[tid];
}

// --------- fused: LN(P) with on_w/on_b, then x1 = x + xs + gamma_s*LN ----------
__global__ void lnres_kernel(const float* __restrict__ P, const float* __restrict__ x,
                             const float* __restrict__ xs, const float* __restrict__ w,
                             const float* __restrict__ b, const float* __restrict__ gamma,
                             float* __restrict__ out)
{
    int row = blockIdx.x;
    int tid = threadIdx.x;
    size_t idx = (size_t)row * CC + tid;
    float v = P[idx];
    float s = v, s2 = v * v;
    #pragma unroll
    for (int o = 16; o; o >>= 1) {
        s  += __shfl_down_sync(0xffffffffu, s,  o);
        s2 += __shfl_down_sync(0xffffffffu, s2, o);
    }
    __shared__ float sa[8], sb[8];
    int lane = tid & 31, wid = tid >> 5;
    if (!lane) { sa[wid] = s; sb[wid] = s2; }
    __syncthreads();
    if (tid < 32) {
        s  = (tid < 8) ? sa[tid] : 0.f;
        s2 = (tid < 8) ? sb[tid] : 0.f;
        #pragma unroll
        for (int o = 4; o; o >>= 1) {
            s  += __shfl_down_sync(0xffffffffu, s,  o);
            s2 += __shfl_down_sync(0xffffffffu, s2, o);
        }
        if (!tid) {
            float mean = s * (1.f / CC);
            float var  = s2 * (1.f / CC) - mean * mean;
            sa[0] = mean;
            sb[0] = rsqrtf(var + LNEPS);
        }
    }
    __syncthreads();
    float ln = (v - sa[0]) * sb[0] * w[tid] + b[tid];
    out[idx] = x[idx] + xs[idx] + gamma[0] * ln;
}

// ---------------- attention per (b,t,head): E=128, D=32, no softmax ------------
__global__ void attn_kernel(const float* __restrict__ Q, const float* __restrict__ K,
                            const float* __restrict__ V, float* __restrict__ O)
{
    __shared__ float4 Ks[1024];
    __shared__ float4 Vs[1024];
    int h  = blockIdx.x & 7;
    int bt = blockIdx.x >> 3;
    int tid = threadIdx.x;          // 0..127 == e
    size_t base = (size_t)bt * EE * CC + h * 32;
    for (int idx = tid; idx < 1024; idx += 128) {
        int f = idx >> 3, i = idx & 7;
        Ks[idx] = *(const float4*)&K[base + (size_t)f * CC + i * 4];
        Vs[idx] = *(const float4*)&V[base + (size_t)f * CC + i * 4];
    }
    float4 q[8], o[8];
    #pragma unroll
    for (int i = 0; i < 8; i++) {
        q[i] = *(const float4*)&Q[base + (size_t)tid * CC + i * 4];
        o[i] = make_float4(0.f, 0.f, 0.f, 0.f);
    }
    __syncthreads();
    const float* mrow = g_maskf + tid * EE;
    for (int f = 0; f < EE; f++) {
        float s = 0.f;
        #pragma unroll
        for (int i = 0; i < 8; i++) {
            float4 k4 = Ks[f * 8 + i];
            s += q[i].x * k4.x + q[i].y * k4.y + q[i].z * k4.z + q[i].w * k4.w;
        }
        float wgt = s * mrow[f] + 0.5f;     // (attn*mask + 1)*0.5
        #pragma unroll
        for (int i = 0; i < 8; i++) {
            float4 v4 = Vs[f * 8 + i];
            o[i].x += wgt * v4.x; o[i].y += wgt * v4.y;
            o[i].z += wgt * v4.z; o[i].w += wgt * v4.w;
        }
    }
    #pragma unroll
    for (int i = 0; i < 8; i++)
        *(float4*)&O[base + (size_t)tid * CC + i * 4] = o[i];
}

// ---------------- tf32 mma.sync GEMM: 128x128 block tile, 8 warps ----------------
// C[M,N] = A[M,K] @ Bt[N,K]^T   (Bt row n = column n of B, K-contiguous)
// Fragment-packed smem layouts (PTX m16n8k8 tf32 mapping):
//   A frag: ((mi*4+kc)*32 + lane)*4 + slot   (uint32), slot = (r>>3) + 2*(c>>2)
//   B frag: ((ni*4+kc)*32 + lane)*2 + slot   (uint32), slot = krel>>2
// Epilogue identical semantics to R1.
static constexpr int MMA_SMEM = 2 * 32768;   // double buffer: A 16KB + B 16KB per buf

template<int KDIM, bool GATHER>
__global__ void __launch_bounds__(256, 2) mma_gemm(
        const float* __restrict__ A, const float* __restrict__ Bt,
        float* __restrict__ C, int N,
        const float* __restrict__ colScale, const float* __restrict__ colShift,
        int doGelu, const float* __restrict__ res, float resCoef,
        const float* __restrict__ vMul)
{
    extern __shared__ __align__(128) char smem[];
    constexpr int NT = KDIM / 32;
    const int tid = threadIdx.x;
    const int w = tid >> 5, lane = tid & 31;
    const int n0 = blockIdx.x * 128, m0 = blockIdx.y * 128;
    const int mib = (w >> 2) * 4;      // m16-tile base within block
    const int nib = (w & 3) * 4;       // n8-tile base within block

    float acc[4][4][4] = {};
    float4 aR[4], bR[4];

    // ---- producers ----
    auto load_tile = [&](int kt) {
        const int k0 = kt * 32;
        #pragma unroll
        for (int i = 0; i < 4; i++) {
            int idx = tid + 256 * i;
            int row = idx >> 3, c4 = idx & 7;
            if (GATHER) {
                int j = k0 >> 8, c0 = k0 & 255;
                int rg = m0 + row;
                int t = (rg >> 7) & 63, tt = t + j - 1;
                aR[i] = make_float4(0.f, 0.f, 0.f, 0.f);
                if ((unsigned)tt < 64u)
                    aR[i] = *(const float4*)&A[((size_t)rg + (ptrdiff_t)(j - 1) * EE) * CC + c0 + c4 * 4];
            } else {
                aR[i] = *(const float4*)&A[(size_t)(m0 + row) * KDIM + k0 + c4 * 4];
            }
            bR[i] = *(const float4*)&Bt[(size_t)(n0 + row) * KDIM + k0 + c4 * 4];
        }
    };
    auto stage = [&](int buf) {
        char* s = smem + buf * 32768;
        #pragma unroll
        for (int i = 0; i < 4; i++) {
            int idx = tid + 256 * i;
            int row = idx >> 3, c4 = idx & 7;
            int kc = c4 >> 1, hi = c4 & 1;
            // A
            int mi = row >> 4, r = row & 15;
            float va[4] = {aR[i].x, aR[i].y, aR[i].z, aR[i].w};
            int slotA = (r >> 3) + 2 * hi;
            #pragma unroll
            for (int e = 0; e < 4; e++) {
                int ln = (r & 7) * 4 + e;
                *(uint32_t*)(s + (((mi * 4 + kc) * 32 + ln) * 4 + slotA) * 4) = f2tf32(va[e]);
            }
            // B (row here = n index)
            int ni = row >> 3, ncol = row & 7;
            float vb[4] = {bR[i].x, bR[i].y, bR[i].z, bR[i].w};
            #pragma unroll
            for (int e = 0; e < 4; e++) {
                int ln = ncol * 4 + e;
                *(uint32_t*)(s + 16384 + (((ni * 4 + kc) * 32 + ln) * 2 + hi) * 4) = f2tf32(vb[e]);
            }
        }
    };
    auto compute = [&](int buf) {
        const char* s = smem + buf * 32768;
        #pragma unroll
        for (int kc = 0; kc < 4; kc++) {
            uint4 af[4];
            uint2 bf[4];
            #pragma unroll
            for (int mi = 0; mi < 4; mi++)
                af[mi] = *(const uint4*)(s + (((mib + mi) * 4 + kc) * 32 + lane) * 16);
            #pragma unroll
            for (int ni = 0; ni < 4; ni++)
                bf[ni] = *(const uint2*)(s + 16384 + (((nib + ni) * 4 + kc) * 32 + lane) * 8);
            #pragma unroll
            for (int mi = 0; mi < 4; mi++)
                #pragma unroll
                for (int ni = 0; ni < 4; ni++)
                    mma8(acc[mi][ni], af[mi], bf[ni]);
        }
    };

    load_tile(0);
    stage(0);
    __syncthreads();
    #pragma unroll 1
    for (int kt = 0; kt < NT; kt++) {
        if (kt + 1 < NT) load_tile(kt + 1);
        compute(kt & 1);
        if (kt + 1 < NT) {
            stage((kt + 1) & 1);
            __syncthreads();
        }
    }

    // ---- epilogue ----
    const float vm = vMul ? *vMul : 1.0f;
    #pragma unroll
    for (int mi = 0; mi < 4; mi++) {
        #pragma unroll
        for (int ni = 0; ni < 4; ni++) {
            int r0 = m0 + (mib + mi) * 16 + (lane >> 2);
            int c0 = n0 + (nib + ni) * 8 + 2 * (lane & 3);
            #pragma unroll
            for (int half = 0; half < 2; half++) {
                int row = r0 + half * 8;
                float v0 = acc[mi][ni][half * 2 + 0];
                float v1 = acc[mi][ni][half * 2 + 1];
                size_t base = (size_t)row * N + c0;
                if (colScale) {
                    v0 = v0 * colScale[c0] + colShift[c0];
                    v1 = v1 * colScale[c0 + 1] + colShift[c0 + 1];
                } else if (colShift) {
                    v0 += colShift[c0];
                    v1 += colShift[c0 + 1];
                }
                if (doGelu) { v0 = gelu_exact(v0); v1 = gelu_exact(v1); }
                if (res) {
                    float2 r2 = *(const float2*)(res + base);
                    v0 = resCoef * r2.x + vm * v0;
                    v1 = resCoef * r2.y + vm * v1;
                }
                *(float2*)(C + base) = make_float2(v0, v1);
            }
        }
    }
}

// -------------------------------- launcher --------------------------------
static float* symaddr(const void* sym)
{
    void* p = nullptr;
    cudaGetSymbolAddress(&p, sym);
    return (float*)p;
}

extern "C" void kernel_launch(void* const* d_in, const int* in_sizes, int n_in,
                              void* d_out, int out_size)
{
    const float* x       = (const float*)d_in[0];
    const int*   adj     = (const int*)  d_in[1];
    const float* n1_w    = (const float*)d_in[2];
    const float* n1_b    = (const float*)d_in[3];
    const float* q_w     = (const float*)d_in[4];
    const float* k_w     = (const float*)d_in[5];
    const float* v_w     = (const float*)d_in[6];
    const float* proj_w  = (const float*)d_in[7];
    const float* proj_b  = (const float*)d_in[8];
    const float* on_w    = (const float*)d_in[9];
    const float* on_b    = (const float*)d_in[10];
    const float* gamma_s = (const float*)d_in[11];
    const float* conv1_w = (const float*)d_in[12];
    const float* bn1_w   = (const float*)d_in[13];
    const float* bn1_b   = (const float*)d_in[14];
    const float* bn1_m   = (const float*)d_in[15];
    const float* bn1_v   = (const float*)d_in[16];
    const float* conv2_w = (const float*)d_in[17];
    const float* bn2_w   = (const float*)d_in[18];
    const float* bn2_b   = (const float*)d_in[19];
    const float* bn2_m   = (const float*)d_in[20];
    const float* bn2_v   = (const float*)d_in[21];
    const float* tn_w    = (const float*)d_in[22];
    const float* tn_b    = (const float*)d_in[23];
    const float* gamma_t = (const float*)d_in[24];
    const float* n3_w    = (const float*)d_in[25];
    const float* n3_b    = (const float*)d_in[26];
    const float* fc1_w   = (const float*)d_in[27];
    const float* fc1_b   = (const float*)d_in[28];
    const float* fc2_w   = (const float*)d_in[29];
    const float* fc2_b   = (const float*)d_in[30];
    float* out = (float*)d_out;

    float* xs  = symaddr(g_xs);
    float* q   = symaddr(g_q);
    float* k   = symaddr(g_k);
    float* v   = symaddr(g_v);
    float* o   = symaddr(g_o);
    float* y1  = symaddr(g_y1);
    float* big = symaddr(g_big);
    float* bq  = symaddr(g_bq);
    float* bk  = symaddr(g_bk);
    float* bv  = symaddr(g_bv);
    float* bp  = symaddr(g_bp);
    float* bw1 = symaddr(g_bw1);
    float* bf1 = symaddr(g_bf1);
    float* bf2 = symaddr(g_bf2);
    float* bn1s = symaddr(g_bn1s);
    float* bn1b = symaddr(g_bn1b);
    float* bn2s = symaddr(g_bn2s);
    float* bn2b = symaddr(g_bn2b);

    cudaFuncSetAttribute(mma_gemm<256, false>,  cudaFuncAttributeMaxDynamicSharedMemorySize, MMA_SMEM);
    cudaFuncSetAttribute(mma_gemm<768, true>,   cudaFuncAttributeMaxDynamicSharedMemorySize, MMA_SMEM);
    cudaFuncSetAttribute(mma_gemm<512, false>,  cudaFuncAttributeMaxDynamicSharedMemorySize, MMA_SMEM);
    cudaFuncSetAttribute(mma_gemm<1024, false>, cudaFuncAttributeMaxDynamicSharedMemorySize, MMA_SMEM);

    // 0) prep
    prep_kernel<<<1536, 256>>>(q_w, k_w, v_w, proj_w, conv1_w, fc1_w, fc2_w, adj,
                               bn1_w, bn1_b, bn1_m, bn1_v,
                               bn2_w, bn2_b, bn2_m, bn2_v);

    // 1) xs = LN(x)
    ln_kernel<<<RROWS, 256>>>(x, n1_w, n1_b, xs);

    // 2) q/k/v
    mma_gemm<256, false><<<dim3(2, 512), 256, MMA_SMEM>>>(xs, bq, q, CC,
        nullptr, nullptr, 0, nullptr, 0.f, nullptr);
    mma_gemm<256, false><<<dim3(2, 512), 256, MMA_SMEM>>>(xs, bk, k, CC,
        nullptr, nullptr, 0, nullptr, 0.f, nullptr);
    mma_gemm<256, false><<<dim3(2, 512), 256, MMA_SMEM>>>(xs, bv, v, CC,
        nullptr, nullptr, 0, nullptr, 0.f, nullptr);

    // 3) masked attention
    attn_kernel<<<BB * TT * NHEAD, 128>>>(q, k, v, o);

    // 4) proj: P = o @ proj_w + proj_b  (into g_q)
    mma_gemm<256, false><<<dim3(2, 512), 256, MMA_SMEM>>>(o, bp, q, CC,
        nullptr, proj_b, 0, nullptr, 0.f, nullptr);

    // 5) x1 = x + xs + gamma_s*LN(P)  (into g_k)
    lnres_kernel<<<RROWS, 256>>>(q, x, xs, on_w, on_b, gamma_s, k);

    // 6) xt = LN(x1)  (into g_xs)
    ln_kernel<<<RROWS, 256>>>(k, tn_w, tn_b, xs);

    // 7) conv1 (gathered) + BN1 + GELU -> y1 [R,512]
    mma_gemm<768, true><<<dim3(4, 512), 256, MMA_SMEM>>>(xs, bw1, y1, HH2,
        bn1s, bn1b, 1, nullptr, 0.f, nullptr);

    // 8) conv2 + BN2, x2 = 2*x1 + gamma_t*y  (into g_v); conv2_w already [c][h]
    mma_gemm<512, false><<<dim3(2, 512), 256, MMA_SMEM>>>(y1, conv2_w, v, CC,
        bn2s, bn2b, 0, k, 2.0f, gamma_t);

    // 9) xm = LN(x2)  (into g_xs)
    ln_kernel<<<RROWS, 256>>>(v, n3_w, n3_b, xs);

    // 10) fc1 + bias + GELU -> big [R,1024]
    mma_gemm<256, false><<<dim3(8, 512), 256, MMA_SMEM>>>(xs, bf1, big, MM,
        nullptr, fc1_b, 1, nullptr, 0.f, nullptr);

    // 11) fc2 + bias + residual x2 -> out
    mma_gemm<1024, false><<<dim3(2, 512), 256, MMA_SMEM>>>(big, bf2, out, CC,
        nullptr, fc2_b, 0, v, 1.0f, nullptr);
}

// round 4
// speedup vs baseline: 3.2871x; 1.5917x over previous
#include <cuda_runtime.h>
#include <cuda_fp16.h>
#include <cstdint>
#include <math.h>

// ---------------- problem constants ----------------
#define BB 8
#define TT 64
#define EE 128
#define CC 256
#define HH2 512          // conv hidden
#define MM 1024          // mlp hidden
#define RROWS 65536      // B*T*E
#define LNEPS 1e-5f

// ---------------- device scratch ----------------
__device__ __align__(128) float  g_xs  [RROWS * CC];    // xs fp32 (residual use)
__device__ __align__(128) __half g_xs16[RROWS * CC];    // xs fp16 (GEMM A)
__device__ __align__(128) float  g_qkv [RROWS * 768];   // q|k|v fp32
__device__ __align__(128) __half g_o16 [RROWS * CC];    // attn out fp16
__device__ __align__(128) float  g_p   [RROWS * CC];    // proj out fp32
__device__ __align__(128) float  g_x1  [RROWS * CC];    // x1 fp32
__device__ __align__(128) __half g_xt16[RROWS * CC];    // LN(x1) fp16
__device__ __align__(128) __half g_y1h [RROWS * HH2];   // conv1 out fp16
__device__ __align__(128) float  g_x2  [RROWS * CC];    // x2 fp32
__device__ __align__(128) __half g_xm16[RROWS * CC];    // LN(x2) fp16
__device__ __align__(128) __half g_bigh[RROWS * MM];    // mlp hidden fp16
// fp16 weights, all [N][K] K-major
__device__ __align__(128) __half g_hqkv[768 * CC];
__device__ __align__(128) __half g_hp  [CC * CC];
__device__ __align__(128) __half g_hw1 [HH2 * 768];     // conv1: [h][kk], kk=j*256+c
__device__ __align__(128) __half g_hw2 [CC * HH2];
__device__ __align__(128) __half g_hf1 [MM * CC];
__device__ __align__(128) __half g_hf2 [CC * MM];
__device__ __align__(128) float g_maskf[EE * EE];       // 0.5 * adj_mask
__device__ __align__(128) float g_bn1s[HH2], g_bn1b[HH2], g_bn2s[CC], g_bn2b[CC];

// ---------------- helpers ----------------
#define SWZ(l) ((l) ^ ((l) >> 3))

__device__ __forceinline__ void mma16(float* d, const uint4& a, const uint2& b)
{
    asm volatile("mma.sync.aligned.m16n8k16.row.col.f32.f16.f16.f32 "
                 "{%0,%1,%2,%3}, {%4,%5,%6,%7}, {%8,%9}, {%0,%1,%2,%3};"
                 : "+f"(d[0]), "+f"(d[1]), "+f"(d[2]), "+f"(d[3])
                 : "r"(a.x), "r"(a.y), "r"(a.z), "r"(a.w), "r"(b.x), "r"(b.y));
}

__device__ __forceinline__ float gelu_exact(float v)
{
    return 0.5f * v * (1.f + erff(v * 0.70710678118654752f));
}

// ---------------- prep ----------------
__global__ void prep_kernel(const float* __restrict__ qw, const float* __restrict__ kw,
                            const float* __restrict__ vw, const float* __restrict__ pw,
                            const float* __restrict__ w1, const float* __restrict__ w2,
                            const float* __restrict__ f1, const float* __restrict__ f2,
                            const int* __restrict__ mask,
                            const float* __restrict__ b1w, const float* __restrict__ b1b,
                            const float* __restrict__ b1m, const float* __restrict__ b1v,
                            const float* __restrict__ b2w, const float* __restrict__ b2b,
                            const float* __restrict__ b2m, const float* __restrict__ b2v)
{
    int idx = blockIdx.x * blockDim.x + threadIdx.x;
    if (idx < 768 * CC) {           // qkv concat [n][k]
        int n = idx >> 8, k = idx & 255;
        const float* src = (n < 256) ? qw : (n < 512) ? kw : vw;
        g_hqkv[idx] = __float2half(src[k * CC + (n & 255)]);
    }
    if (idx < CC * CC) {
        int n = idx >> 8, k = idx & 255;
        g_hp[idx] = __float2half(pw[k * CC + n]);
    }
    if (idx < HH2 * 768) {
        int h = idx / 768, kk = idx % 768;
        int j = kk >> 8, c = kk & 255;
        g_hw1[idx] = __float2half(w1[h * 768 + c * 3 + j]);
    }
    if (idx < CC * HH2) g_hw2[idx] = __float2half(w2[idx]);   // already [c][h]
    if (idx < MM * CC) {
        int n = idx >> 8, k = idx & 255;
        g_hf1[idx] = __float2half(f1[k * MM + n]);
    }
    if (idx < CC * MM) {
        int n = idx >> 10, k = idx & 1023;
        g_hf2[idx] = __float2half(f2[k * CC + n]);
    }
    if (idx < EE * EE) g_maskf[idx] = 0.5f * (float)mask[idx];
    if (idx < HH2) {
        float s = b1w[idx] * rsqrtf(b1v[idx] + LNEPS);
        g_bn1s[idx] = s;
        g_bn1b[idx] = b1b[idx] - b1m[idx] * s;
    }
    if (idx < CC) {
        float s = b2w[idx] * rsqrtf(b2v[idx] + LNEPS);
        g_bn2s[idx] = s;
        g_bn2b[idx] = b2b[idx] - b2m[idx] * s;
    }
}

// ---------------- row reduce (mean, rstd) ----------------
__device__ __forceinline__ void row_stats(float v, int tid, float& mean, float& rstd)
{
    float s = v, s2 = v * v;
    #pragma unroll
    for (int o = 16; o; o >>= 1) {
        s  += __shfl_down_sync(0xffffffffu, s,  o);
        s2 += __shfl_down_sync(0xffffffffu, s2, o);
    }
    __shared__ float sa[8], sb[8];
    int lane = tid & 31, wid = tid >> 5;
    if (!lane) { sa[wid] = s; sb[wid] = s2; }
    __syncthreads();
    if (tid < 32) {
        s  = (tid < 8) ? sa[tid] : 0.f;
        s2 = (tid < 8) ? sb[tid] : 0.f;
        #pragma unroll
        for (int o = 4; o; o >>= 1) {
            s  += __shfl_down_sync(0xffffffffu, s,  o);
            s2 += __shfl_down_sync(0xffffffffu, s2, o);
        }
        if (!tid) {
            float m = s * (1.f / CC);
            sa[0] = m;
            sb[0] = rsqrtf(s2 * (1.f / CC) - m * m + LNEPS);
        }
    }
    __syncthreads();
    mean = sa[0]; rstd = sb[0];
}

// LN -> fp32 + fp16 outputs
__global__ void ln_dual_kernel(const float* __restrict__ in, const float* __restrict__ w,
                               const float* __restrict__ b, float* __restrict__ o32,
                               __half* __restrict__ o16)
{
    int tid = threadIdx.x;
    size_t idx = (size_t)blockIdx.x * CC + tid;
    float v = in[idx];
    float mean, rstd;
    row_stats(v, tid, mean, rstd);
    float r = (v - mean) * rstd * w[tid] + b[tid];
    o32[idx] = r;
    o16[idx] = __float2half(r);
}

// LN -> fp16 only
__global__ void ln_h_kernel(const float* __restrict__ in, const float* __restrict__ w,
                            const float* __restrict__ b, __half* __restrict__ o16)
{
    int tid = threadIdx.x;
    size_t idx = (size_t)blockIdx.x * CC + tid;
    float v = in[idx];
    float mean, rstd;
    row_stats(v, tid, mean, rstd);
    o16[idx] = __float2half((v - mean) * rstd * w[tid] + b[tid]);
}

// x1 = x + xs + gamma_s*LN(P)
__global__ void lnres_kernel(const float* __restrict__ P, const float* __restrict__ x,
                             const float* __restrict__ xs, const float* __restrict__ w,
                             const float* __restrict__ b, const float* __restrict__ gamma,
                             float* __restrict__ out)
{
    int tid = threadIdx.x;
    size_t idx = (size_t)blockIdx.x * CC + tid;
    float v = P[idx];
    float mean, rstd;
    row_stats(v, tid, mean, rstd);
    float ln = (v - mean) * rstd * w[tid] + b[tid];
    out[idx] = x[idx] + xs[idx] + gamma[0] * ln;
}

// ---------------- attention per (b,t,head): E=128, D=32 ------------
__global__ void attn_kernel(const float* __restrict__ QKV, __half* __restrict__ O)
{
    __shared__ float4 Ks[1024];
    __shared__ float4 Vs[1024];
    int h  = blockIdx.x & 7;
    int bt = blockIdx.x >> 3;
    int tid = threadIdx.x;          // == e
    size_t base = (size_t)bt * EE * 768 + h * 32;
    for (int idx = tid; idx < 1024; idx += 128) {
        int f = idx >> 3, i = idx & 7;
        Ks[idx] = *(const float4*)&QKV[base + 256 + (size_t)f * 768 + i * 4];
        Vs[idx] = *(const float4*)&QKV[base + 512 + (size_t)f * 768 + i * 4];
    }
    float4 q[8], o[8];
    #pragma unroll
    for (int i = 0; i < 8; i++) {
        q[i] = *(const float4*)&QKV[base + (size_t)tid * 768 + i * 4];
        o[i] = make_float4(0.f, 0.f, 0.f, 0.f);
    }
    __syncthreads();
    const float* mrow = g_maskf + tid * EE;
    for (int f = 0; f < EE; f++) {
        float s = 0.f;
        #pragma unroll
        for (int i = 0; i < 8; i++) {
            float4 k4 = Ks[f * 8 + i];
            s += q[i].x * k4.x + q[i].y * k4.y + q[i].z * k4.z + q[i].w * k4.w;
        }
        float wgt = s * mrow[f] + 0.5f;
        #pragma unroll
        for (int i = 0; i < 8; i++) {
            float4 v4 = Vs[f * 8 + i];
            o[i].x += wgt * v4.x; o[i].y += wgt * v4.y;
            o[i].z += wgt * v4.z; o[i].w += wgt * v4.w;
        }
    }
    size_t obase = (size_t)bt * EE * CC + (size_t)tid * CC + h * 32;
    #pragma unroll
    for (int i = 0; i < 8; i++) {
        __half2 h0 = __floats2half2_rn(o[i].x, o[i].y);
        __half2 h1 = __floats2half2_rn(o[i].z, o[i].w);
        *(uint2*)&O[obase + i * 4] = make_uint2(*(uint32_t*)&h0, *(uint32_t*)&h1);
    }
}

// ---------------- fp16 mma GEMM: CTA 256x128, 512 threads, 4m x 4n warps -------
// C[M,N] = A[M,K] @ Bt[N,K]^T, A/Bt fp16, fp32 accumulate.
// smem per buffer: A frag-packed 16KB + B frag-packed 8KB; double buffered = 48KB.
static constexpr int HG_SMEM = 49152;

template<int KDIM, bool GATHER, bool OUTH>
__global__ void __launch_bounds__(512, 1) h_gemm(
        const __half* __restrict__ A, const __half* __restrict__ Bt,
        void* __restrict__ Cv, int N,
        const float* __restrict__ colScale, const float* __restrict__ colShift,
        int doGelu, const float* __restrict__ res, float resCoef,
        const float* __restrict__ vMul)
{
    extern __shared__ __align__(128) char smem[];
    constexpr int NT = KDIM / 32;
    const int tid = threadIdx.x;
    const int w = tid >> 5, lane = tid & 31;
    const int n0 = blockIdx.x * 128, m0 = blockIdx.y * 256;
    const int mg = w >> 2, ng = w & 3;

    // ---- A staging items (2 per thread): id = mi*64 + rl*8 + c4 ----
    int aMi[2], aRl[2], aC4[2], aDst0[2], aDst1[2], aRow[2];
    #pragma unroll
    for (int it = 0; it < 2; it++) {
        int id = tid + it * 512;
        int mi = id >> 6, rl = (id >> 3) & 7, c4 = id & 7;
        int ks = c4 >> 2;
        int lane_a = rl * 4 + (c4 & 1) * 2;
        int regb = 2 * ((c4 & 3) >> 1);
        int fA = mi * 2 + ks;
        aMi[it] = mi; aRl[it] = rl; aC4[it] = c4;
        aRow[it] = m0 + mi * 16 + rl;
        aDst0[it] = fA * 512 + SWZ(lane_a) * 16 + regb * 4;
        aDst1[it] = fA * 512 + SWZ(lane_a + 1) * 16 + regb * 4;
    }
    // ---- B staging item (1 per thread): id = n*4 + c2 ----
    const int bN  = tid >> 2;
    const int bC2 = tid & 3;
    const int bKs = bC2 >> 1;
    const int bK0 = bKs * 16 + (bC2 & 1) * 4;
    const int bLane = (bN & 7) * 4 + (bC2 & 1) * 2;
    const int bDst = 16384 + ((bN >> 3) * 2 + bKs) * 256 + bLane * 8;
    const __half* bSrc = Bt + (size_t)(n0 + bN) * KDIM + bK0;

    float acc[4][4][4] = {};
    uint2 aLo[2], aHi[2], bLo, bHi;

    auto load_tile = [&](int kt) {
        #pragma unroll
        for (int it = 0; it < 2; it++) {
            int klocal = aC4[it] * 4;
            if (GATHER) {
                int kg = kt * 32 + klocal;
                int j = kg >> 8, c = kg & 255;
                int t = (aRow[it] >> 7) & 63;
                int tt = t + j - 1;
                aLo[it] = make_uint2(0, 0); aHi[it] = make_uint2(0, 0);
                if ((unsigned)tt < 64u) {
                    const __half* src = A + ((size_t)aRow[it] + (ptrdiff_t)(j - 1) * EE) * CC + c;
                    aLo[it] = *(const uint2*)src;
                    aHi[it] = *(const uint2*)(src + 8 * CC);
                }
            } else {
                const __half* src = A + (size_t)aRow[it] * KDIM + kt * 32 + klocal;
                aLo[it] = *(const uint2*)src;
                aHi[it] = *(const uint2*)(src + 8 * KDIM);
            }
        }
        bLo = *(const uint2*)(bSrc + kt * 32);
        bHi = *(const uint2*)(bSrc + kt * 32 + 8);
    };
    auto stage = [&](int buf) {
        char* s = smem + buf * 24576;
        #pragma unroll
        for (int it = 0; it < 2; it++) {
            *(uint2*)(s + aDst0[it]) = make_uint2(aLo[it].x, aHi[it].x);
            *(uint2*)(s + aDst1[it]) = make_uint2(aLo[it].y, aHi[it].y);
        }
        *(uint4*)(s + bDst) = make_uint4(bLo.x, bHi.x, bLo.y, bHi.y);
    };
    auto compute = [&](int buf) {
        const char* s = smem + buf * 24576;
        const int swl = SWZ(lane);
        #pragma unroll
        for (int ks = 0; ks < 2; ks++) {
            uint4 af[4];
            uint2 bf[4];
            #pragma unroll
            for (int mi = 0; mi < 4; mi++)
                af[mi] = *(const uint4*)(s + ((mg * 4 + mi) * 2 + ks) * 512 + swl * 16);
            #pragma unroll
            for (int ni = 0; ni < 4; ni++)
                bf[ni] = *(const uint2*)(s + 16384 + ((ng * 4 + ni) * 2 + ks) * 256 + lane * 8);
            #pragma unroll
            for (int mi = 0; mi < 4; mi++)
                #pragma unroll
                for (int ni = 0; ni < 4; ni++)
                    mma16(acc[mi][ni], af[mi], bf[ni]);
        }
    };

    load_tile(0);
    stage(0);
    __syncthreads();
    #pragma unroll 1
    for (int kt = 0; kt < NT; kt++) {
        if (kt + 1 < NT) load_tile(kt + 1);
        compute(kt & 1);
        if (kt + 1 < NT) {
            stage((kt + 1) & 1);
            __syncthreads();
        }
    }

    // ---- epilogue ----
    const float vm = vMul ? *vMul : 1.0f;
    #pragma unroll
    for (int mi = 0; mi < 4; mi++) {
        #pragma unroll
        for (int ni = 0; ni < 4; ni++) {
            int r0 = m0 + (mg * 4 + mi) * 16 + (lane >> 2);
            int c0 = n0 + (ng * 4 + ni) * 8 + 2 * (lane & 3);
            #pragma unroll
            for (int half = 0; half < 2; half++) {
                int row = r0 + half * 8;
                float v0 = acc[mi][ni][half * 2 + 0];
                float v1 = acc[mi][ni][half * 2 + 1];
                size_t base = (size_t)row * N + c0;
                if (colScale) {
                    v0 = v0 * colScale[c0] + colShift[c0];
                    v1 = v1 * colScale[c0 + 1] + colShift[c0 + 1];
                } else if (colShift) {
                    v0 += colShift[c0];
                    v1 += colShift[c0 + 1];
                }
                if (doGelu) { v0 = gelu_exact(v0); v1 = gelu_exact(v1); }
                if (res) {
                    float2 r2 = *(const float2*)(res + base);
                    v0 = resCoef * r2.x + vm * v0;
                    v1 = resCoef * r2.y + vm * v1;
                }
                if (OUTH) {
                    __half2 h2v = __floats2half2_rn(v0, v1);
                    *(__half2*)((__half*)Cv + base) = h2v;
                } else {
                    *(float2*)((float*)Cv + base) = make_float2(v0, v1);
                }
            }
        }
    }
}

// -------------------------------- launcher --------------------------------
template<typename T>
static T* symaddr(const void* sym)
{
    void* p = nullptr;
    cudaGetSymbolAddress(&p, sym);
    return (T*)p;
}

extern "C" void kernel_launch(void* const* d_in, const int* in_sizes, int n_in,
                              void* d_out, int out_size)
{
    const float* x       = (const float*)d_in[0];
    const int*   adj     = (const int*)  d_in[1];
    const float* n1_w    = (const float*)d_in[2];
    const float* n1_b    = (const float*)d_in[3];
    const float* q_w     = (const float*)d_in[4];
    const float* k_w     = (const float*)d_in[5];
    const float* v_w     = (const float*)d_in[6];
    const float* proj_w  = (const float*)d_in[7];
    const float* proj_b  = (const float*)d_in[8];
    const float* on_w    = (const float*)d_in[9];
    const float* on_b    = (const float*)d_in[10];
    const float* gamma_s = (const float*)d_in[11];
    const float* conv1_w = (const float*)d_in[12];
    const float* bn1_w   = (const float*)d_in[13];
    const float* bn1_b   = (const float*)d_in[14];
    const float* bn1_m   = (const float*)d_in[15];
    const float* bn1_v   = (const float*)d_in[16];
    const float* conv2_w = (const float*)d_in[17];
    const float* bn2_w   = (const float*)d_in[18];
    const float* bn2_b   = (const float*)d_in[19];
    const float* bn2_m   = (const float*)d_in[20];
    const float* bn2_v   = (const float*)d_in[21];
    const float* tn_w    = (const float*)d_in[22];
    const float* tn_b    = (const float*)d_in[23];
    const float* gamma_t = (const float*)d_in[24];
    const float* n3_w    = (const float*)d_in[25];
    const float* n3_b    = (const float*)d_in[26];
    const float* fc1_w   = (const float*)d_in[27];
    const float* fc1_b   = (const float*)d_in[28];
    const float* fc2_w   = (const float*)d_in[29];
    const float* fc2_b   = (const float*)d_in[30];
    float* out = (float*)d_out;

    float*  xs   = symaddr<float >(g_xs);
    __half* xs16 = symaddr<__half>(g_xs16);
    float*  qkv  = symaddr<float >(g_qkv);
    __half* o16  = symaddr<__half>(g_o16);
    float*  p    = symaddr<float >(g_p);
    float*  x1   = symaddr<float >(g_x1);
    __half* xt16 = symaddr<__half>(g_xt16);
    __half* y1h  = symaddr<__half>(g_y1h);
    float*  x2   = symaddr<float >(g_x2);
    __half* xm16 = symaddr<__half>(g_xm16);
    __half* bigh = symaddr<__half>(g_bigh);
    __half* hqkv = symaddr<__half>(g_hqkv);
    __half* hp   = symaddr<__half>(g_hp);
    __half* hw1  = symaddr<__half>(g_hw1);
    __half* hw2  = symaddr<__half>(g_hw2);
    __half* hf1  = symaddr<__half>(g_hf1);
    __half* hf2  = symaddr<__half>(g_hf2);
    float* bn1s = symaddr<float>(g_bn1s);
    float* bn1b = symaddr<float>(g_bn1b);
    float* bn2s = symaddr<float>(g_bn2s);
    float* bn2b = symaddr<float>(g_bn2b);

    cudaFuncSetAttribute(h_gemm<256,  false, false>, cudaFuncAttributeMaxDynamicSharedMemorySize, HG_SMEM);
    cudaFuncSetAttribute(h_gemm<256,  false, true >, cudaFuncAttributeMaxDynamicSharedMemorySize, HG_SMEM);
    cudaFuncSetAttribute(h_gemm<768,  true,  true >, cudaFuncAttributeMaxDynamicSharedMemorySize, HG_SMEM);
    cudaFuncSetAttribute(h_gemm<512,  false, false>, cudaFuncAttributeMaxDynamicSharedMemorySize, HG_SMEM);
    cudaFuncSetAttribute(h_gemm<1024, false, false>, cudaFuncAttributeMaxDynamicSharedMemorySize, HG_SMEM);

    // 0) prep: fp16 weight transposes + BN folding + mask
    prep_kernel<<<1536, 256>>>(q_w, k_w, v_w, proj_w, conv1_w, conv2_w, fc1_w, fc2_w, adj,
                               bn1_w, bn1_b, bn1_m, bn1_v,
                               bn2_w, bn2_b, bn2_m, bn2_v);

    // 1) xs = LN(x)  (fp32 + fp16)
    ln_dual_kernel<<<RROWS, 256>>>(x, n1_w, n1_b, xs, xs16);

    // 2) fused QKV GEMM -> [R][768] fp32
    h_gemm<256, false, false><<<dim3(6, 256), 512, HG_SMEM>>>(xs16, hqkv, qkv, 768,
        nullptr, nullptr, 0, nullptr, 0.f, nullptr);

    // 3) masked attention -> o16
    attn_kernel<<<BB * TT * 8, 128>>>(qkv, o16);

    // 4) proj: P = o @ proj_w + proj_b
    h_gemm<256, false, false><<<dim3(2, 256), 512, HG_SMEM>>>(o16, hp, p, CC,
        nullptr, proj_b, 0, nullptr, 0.f, nullptr);

    // 5) x1 = x + xs + gamma_s*LN(P)
    lnres_kernel<<<RROWS, 256>>>(p, x, xs, on_w, on_b, gamma_s, x1);

    // 6) xt = LN(x1) fp16
    ln_h_kernel<<<RROWS, 256>>>(x1, tn_w, tn_b, xt16);

    // 7) conv1 (gathered) + BN1 + GELU -> y1 fp16
    h_gemm<768, true, true><<<dim3(4, 256), 512, HG_SMEM>>>(xt16, hw1, y1h, HH2,
        bn1s, bn1b, 1, nullptr, 0.f, nullptr);

    // 8) conv2 + BN2, x2 = 2*x1 + gamma_t*y
    h_gemm<512, false, false><<<dim3(2, 256), 512, HG_SMEM>>>(y1h, hw2, x2, CC,
        bn2s, bn2b, 0, x1, 2.0f, gamma_t);

    // 9) xm = LN(x2) fp16
    ln_h_kernel<<<RROWS, 256>>>(x2, n3_w, n3_b, xm16);

    // 10) fc1 + bias + GELU -> big fp16
    h_gemm<256, false, true><<<dim3(8, 256), 512, HG_SMEM>>>(xm16, hf1, bigh, MM,
        nullptr, fc1_b, 1, nullptr, 0.f, nullptr);

    // 11) fc2 + bias + residual x2 -> out fp32
    h_gemm<1024, false, false><<<dim3(2, 256), 512, HG_SMEM>>>(bigh, hf2, out, CC,
        nullptr, fc2_b, 0, x2, 1.0f, nullptr);
}

// round 5
// speedup vs baseline: 4.3404x; 1.3204x over previous
#include <cuda_runtime.h>
#include <cuda_fp16.h>
#include <cstdint>
#include <math.h>

// ---------------- problem constants ----------------
#define BB 8
#define TT 64
#define EE 128
#define CC 256
#define HH2 512          // conv hidden
#define MM 1024          // mlp hidden
#define RROWS 65536      // B*T*E
#define LNEPS 1e-5f

// ---------------- device scratch ----------------
__device__ __align__(128) float  g_xs  [RROWS * CC];    // xs fp32 (residual use)
__device__ __align__(128) __half g_xs16[RROWS * CC];    // xs fp16 (GEMM A)
__device__ __align__(128) __half g_qkvh[RROWS * 768];   // q|k|v fp16
__device__ __align__(128) __half g_o16 [RROWS * CC];    // attn out fp16
__device__ __align__(128) float  g_p   [RROWS * CC];    // proj out fp32
__device__ __align__(128) float  g_x1  [RROWS * CC];    // x1 fp32
__device__ __align__(128) __half g_xt16[RROWS * CC];    // LN(x1) fp16
__device__ __align__(128) __half g_y1h [RROWS * HH2];   // conv1 out fp16
__device__ __align__(128) float  g_x2  [RROWS * CC];    // x2 fp32
__device__ __align__(128) __half g_xm16[RROWS * CC];    // LN(x2) fp16
__device__ __align__(128) __half g_bigh[RROWS * MM];    // mlp hidden fp16
// fp16 weights, all [N][K] K-major
__device__ __align__(128) __half g_hqkv[768 * CC];
__device__ __align__(128) __half g_hp  [CC * CC];
__device__ __align__(128) __half g_hw1 [HH2 * 768];     // conv1: [h][kk], kk=j*256+c
__device__ __align__(128) __half g_hw2 [CC * HH2];
__device__ __align__(128) __half g_hf1 [MM * CC];
__device__ __align__(128) __half g_hf2 [CC * MM];
__device__ __align__(128) float g_maskf[EE * EE];       // 0.5 * adj_mask
__device__ __align__(128) float g_bn1s[HH2], g_bn1b[HH2], g_bn2s[CC], g_bn2b[CC];

// ---------------- helpers ----------------
#define SWZ(l) ((l) ^ ((l) >> 3))

__device__ __forceinline__ void mma16(float* d, const uint4& a, const uint2& b)
{
    asm volatile("mma.sync.aligned.m16n8k16.row.col.f32.f16.f16.f32 "
                 "{%0,%1,%2,%3}, {%4,%5,%6,%7}, {%8,%9}, {%0,%1,%2,%3};"
                 : "+f"(d[0]), "+f"(d[1]), "+f"(d[2]), "+f"(d[3])
                 : "r"(a.x), "r"(a.y), "r"(a.z), "r"(a.w), "r"(b.x), "r"(b.y));
}

__device__ __forceinline__ float gelu_exact(float v)
{
    return 0.5f * v * (1.f + erff(v * 0.70710678118654752f));
}

// ---------------- prep ----------------
__global__ void prep_kernel(const float* __restrict__ qw, const float* __restrict__ kw,
                            const float* __restrict__ vw, const float* __restrict__ pw,
                            const float* __restrict__ w1, const float* __restrict__ w2,
                            const float* __restrict__ f1, const float* __restrict__ f2,
                            const int* __restrict__ mask,
                            const float* __restrict__ b1w, const float* __restrict__ b1b,
                            const float* __restrict__ b1m, const float* __restrict__ b1v,
                            const float* __restrict__ b2w, const float* __restrict__ b2b,
                            const float* __restrict__ b2m, const float* __restrict__ b2v)
{
    int idx = blockIdx.x * blockDim.x + threadIdx.x;
    if (idx < 768 * CC) {           // qkv concat [n][k]
        int n = idx >> 8, k = idx & 255;
        const float* src = (n < 256) ? qw : (n < 512) ? kw : vw;
        g_hqkv[idx] = __float2half(src[k * CC + (n & 255)]);
    }
    if (idx < CC * CC) {
        int n = idx >> 8, k = idx & 255;
        g_hp[idx] = __float2half(pw[k * CC + n]);
    }
    if (idx < HH2 * 768) {
        int h = idx / 768, kk = idx % 768;
        int j = kk >> 8, c = kk & 255;
        g_hw1[idx] = __float2half(w1[h * 768 + c * 3 + j]);
    }
    if (idx < CC * HH2) g_hw2[idx] = __float2half(w2[idx]);   // already [c][h]
    if (idx < MM * CC) {
        int n = idx >> 8, k = idx & 255;
        g_hf1[idx] = __float2half(f1[k * MM + n]);
    }
    if (idx < CC * MM) {
        int n = idx >> 10, k = idx & 1023;
        g_hf2[idx] = __float2half(f2[k * CC + n]);
    }
    if (idx < EE * EE) g_maskf[idx] = 0.5f * (float)mask[idx];
    if (idx < HH2) {
        float s = b1w[idx] * rsqrtf(b1v[idx] + LNEPS);
        g_bn1s[idx] = s;
        g_bn1b[idx] = b1b[idx] - b1m[idx] * s;
    }
    if (idx < CC) {
        float s = b2w[idx] * rsqrtf(b2v[idx] + LNEPS);
        g_bn2s[idx] = s;
        g_bn2b[idx] = b2b[idx] - b2m[idx] * s;
    }
}

// ---------------- row reduce (mean, rstd) ----------------
__device__ __forceinline__ void row_stats(float v, int tid, float& mean, float& rstd)
{
    float s = v, s2 = v * v;
    #pragma unroll
    for (int o = 16; o; o >>= 1) {
        s  += __shfl_down_sync(0xffffffffu, s,  o);
        s2 += __shfl_down_sync(0xffffffffu, s2, o);
    }
    __shared__ float sa[8], sb[8];
    int lane = tid & 31, wid = tid >> 5;
    if (!lane) { sa[wid] = s; sb[wid] = s2; }
    __syncthreads();
    if (tid < 32) {
        s  = (tid < 8) ? sa[tid] : 0.f;
        s2 = (tid < 8) ? sb[tid] : 0.f;
        #pragma unroll
        for (int o = 4; o; o >>= 1) {
            s  += __shfl_down_sync(0xffffffffu, s,  o);
            s2 += __shfl_down_sync(0xffffffffu, s2, o);
        }
        if (!tid) {
            float m = s * (1.f / CC);
            sa[0] = m;
            sb[0] = rsqrtf(s2 * (1.f / CC) - m * m + LNEPS);
        }
    }
    __syncthreads();
    mean = sa[0]; rstd = sb[0];
}

__global__ void ln_dual_kernel(const float* __restrict__ in, const float* __restrict__ w,
                               const float* __restrict__ b, float* __restrict__ o32,
                               __half* __restrict__ o16)
{
    int tid = threadIdx.x;
    size_t idx = (size_t)blockIdx.x * CC + tid;
    float v = in[idx];
    float mean, rstd;
    row_stats(v, tid, mean, rstd);
    float r = (v - mean) * rstd * w[tid] + b[tid];
    o32[idx] = r;
    o16[idx] = __float2half(r);
}

__global__ void ln_h_kernel(const float* __restrict__ in, const float* __restrict__ w,
                            const float* __restrict__ b, __half* __restrict__ o16)
{
    int tid = threadIdx.x;
    size_t idx = (size_t)blockIdx.x * CC + tid;
    float v = in[idx];
    float mean, rstd;
    row_stats(v, tid, mean, rstd);
    o16[idx] = __float2half((v - mean) * rstd * w[tid] + b[tid]);
}

__global__ void lnres_kernel(const float* __restrict__ P, const float* __restrict__ x,
                             const float* __restrict__ xs, const float* __restrict__ w,
                             const float* __restrict__ b, const float* __restrict__ gamma,
                             float* __restrict__ out)
{
    int tid = threadIdx.x;
    size_t idx = (size_t)blockIdx.x * CC + tid;
    float v = P[idx];
    float mean, rstd;
    row_stats(v, tid, mean, rstd);
    float ln = (v - mean) * rstd * w[tid] + b[tid];
    out[idx] = x[idx] + xs[idx] + gamma[0] * ln;
}

// ---------------- tensor-core attention: CTA per (b,t), 8 warps, loop heads ----
// Per head: S[128,128] = Q Kt (D=32), W = S*mask+0.5 (fp16), O[128,32] = W V.
// Warp owns 16 e-rows. K-split: two 64-wide f phases (S acc stays at 32 regs).
#define MSTR 136
#define QSTR 40
#define VSTR 136
static constexpr int ATT_SMEM = 64000;   // bytes: mask 34816 + Q 10240 + K 10240 + Vt 8704

__global__ void __launch_bounds__(256, 2) attn_mma(const __half* __restrict__ QKV,
                                                   __half* __restrict__ O)
{
    extern __shared__ __align__(128) __half sm[];
    __half* maskS = sm;                  // [128][MSTR]
    __half* Qs = sm + 17408;             // [128][QSTR]
    __half* Ks = Qs + 5120;
    __half* Vt = Ks + 5120;              // [32][VSTR]
    const int tid = threadIdx.x, w = tid >> 5, lane = tid & 31;
    const int bt = blockIdx.x;
    const int r = lane >> 2, c = lane & 3;
    const int eBase = w * 16;

    // stage mask once (float -> half), padded stride
    for (int i = tid; i < 128 * 32; i += 256) {
        int e = i >> 5, f4 = (i & 31) * 4;
        float4 mv = *(const float4*)&g_maskf[e * 128 + f4];
        __half2 h0 = __floats2half2_rn(mv.x, mv.y);
        __half2 h1 = __floats2half2_rn(mv.z, mv.w);
        *(uint2*)&maskS[e * MSTR + f4] = make_uint2(*(uint32_t*)&h0, *(uint32_t*)&h1);
    }
    __syncthreads();

    const __half* qbase = QKV + (size_t)bt * 128 * 768;
    const int se = tid >> 1, sp = tid & 1;    // staging: 2 threads per row

    for (int h = 0; h < 8; h++) {
        // ---- stage Q, K (row-major padded) and V transposed ----
        {
            const __half* row = qbase + (size_t)se * 768 + h * 32 + sp * 16;
            uint4 q0 = *(const uint4*)(row);
            uint4 q1 = *(const uint4*)(row + 8);
            *(uint4*)&Qs[se * QSTR + sp * 16]     = q0;
            *(uint4*)&Qs[se * QSTR + sp * 16 + 8] = q1;
            uint4 k0 = *(const uint4*)(row + 256);
            uint4 k1 = *(const uint4*)(row + 264);
            *(uint4*)&Ks[se * QSTR + sp * 16]     = k0;
            *(uint4*)&Ks[se * QSTR + sp * 16 + 8] = k1;
            uint4 v0 = *(const uint4*)(row + 512);
            uint4 v1 = *(const uint4*)(row + 520);
            const __half* vh0 = (const __half*)&v0;
            const __half* vh1 = (const __half*)&v1;
            #pragma unroll
            for (int i = 0; i < 8; i++) {
                Vt[(sp * 16 + i) * VSTR + se]     = vh0[i];
                Vt[(sp * 16 + 8 + i) * VSTR + se] = vh1[i];
            }
        }
        __syncthreads();

        // Q A-fragments (2 k-steps over D=32)
        uint4 aQ[2];
        #pragma unroll
        for (int ks = 0; ks < 2; ks++) {
            const __half* q0 = &Qs[(eBase + r) * QSTR + ks * 16 + 2 * c];
            aQ[ks].x = *(const uint32_t*)q0;
            aQ[ks].y = *(const uint32_t*)(q0 + 8 * QSTR);
            aQ[ks].z = *(const uint32_t*)(q0 + 8);
            aQ[ks].w = *(const uint32_t*)(q0 + 8 * QSTR + 8);
        }

        float oacc[4][4] = {};
        #pragma unroll
        for (int ph = 0; ph < 2; ph++) {
            // S = Q Kt over f in [ph*64, ph*64+64)
            float sacc[8][4] = {};
            #pragma unroll
            for (int nt = 0; nt < 8; nt++) {
                const __half* kp = &Ks[(ph * 64 + nt * 8 + r) * QSTR + 2 * c];
                #pragma unroll
                for (int ks = 0; ks < 2; ks++) {
                    uint2 bf;
                    bf.x = *(const uint32_t*)(kp + ks * 16);
                    bf.y = *(const uint32_t*)(kp + ks * 16 + 8);
                    mma16(sacc[nt], aQ[ks], bf);
                }
            }
            // W = S*mask + 0.5, pack accumulators into A-fragment layout (fp16)
            uint32_t wh[8][2];
            #pragma unroll
            for (int nt = 0; nt < 8; nt++) {
                int fb = ph * 64 + nt * 8 + 2 * c;
                float2 m0 = __half22float2(*(__half2*)&maskS[(eBase + r) * MSTR + fb]);
                float2 m1 = __half22float2(*(__half2*)&maskS[(eBase + r + 8) * MSTR + fb]);
                __half2 w0 = __floats2half2_rn(sacc[nt][0] * m0.x + 0.5f,
                                               sacc[nt][1] * m0.y + 0.5f);
                __half2 w1 = __floats2half2_rn(sacc[nt][2] * m1.x + 0.5f,
                                               sacc[nt][3] * m1.y + 0.5f);
                wh[nt][0] = *(uint32_t*)&w0;
                wh[nt][1] = *(uint32_t*)&w1;
            }
            // O += W V over this f range
            #pragma unroll
            for (int kk = 0; kk < 4; kk++) {
                uint4 aw = make_uint4(wh[2 * kk][0], wh[2 * kk][1],
                                      wh[2 * kk + 1][0], wh[2 * kk + 1][1]);
                #pragma unroll
                for (int dt = 0; dt < 4; dt++) {
                    const __half* vp = &Vt[(dt * 8 + r) * VSTR + ph * 64 + kk * 16 + 2 * c];
                    uint2 bf;
                    bf.x = *(const uint32_t*)vp;
                    bf.y = *(const uint32_t*)(vp + 8);
                    mma16(oacc[dt], aw, bf);
                }
            }
        }
        // ---- epilogue: write O rows (fp16) ----
        size_t ob = ((size_t)bt * 128 + eBase + r) * 256 + h * 32;
        #pragma unroll
        for (int dt = 0; dt < 4; dt++) {
            __half2 o0 = __floats2half2_rn(oacc[dt][0], oacc[dt][1]);
            __half2 o1 = __floats2half2_rn(oacc[dt][2], oacc[dt][3]);
            *(uint32_t*)&O[ob + dt * 8 + 2 * c]           = *(uint32_t*)&o0;
            *(uint32_t*)&O[ob + 8 * 256 + dt * 8 + 2 * c] = *(uint32_t*)&o1;
        }
        __syncthreads();
    }
}

// ---------------- fp16 mma GEMM: CTA 256x128, 512 threads, 4m x 4n warps -------
static constexpr int HG_SMEM = 49152;

template<int KDIM, bool GATHER, bool OUTH>
__global__ void __launch_bounds__(512, 1) h_gemm(
        const __half* __restrict__ A, const __half* __restrict__ Bt,
        void* __restrict__ Cv, int N,
        const float* __restrict__ colScale, const float* __restrict__ colShift,
        int doGelu, const float* __restrict__ res, float resCoef,
        const float* __restrict__ vMul)
{
    extern __shared__ __align__(128) char smem[];
    constexpr int NT = KDIM / 32;
    const int tid = threadIdx.x;
    const int w = tid >> 5, lane = tid & 31;
    const int n0 = blockIdx.x * 128, m0 = blockIdx.y * 256;
    const int mg = w >> 2, ng = w & 3;

    int aC4[2], aDst0[2], aDst1[2], aRow[2];
    #pragma unroll
    for (int it = 0; it < 2; it++) {
        int id = tid + it * 512;
        int mi = id >> 6, rl = (id >> 3) & 7, c4 = id & 7;
        int ks = c4 >> 2;
        int lane_a = rl * 4 + (c4 & 1) * 2;
        int regb = 2 * ((c4 & 3) >> 1);
        int fA = mi * 2 + ks;
        aC4[it] = c4;
        aRow[it] = m0 + mi * 16 + rl;
        aDst0[it] = fA * 512 + SWZ(lane_a) * 16 + regb * 4;
        aDst1[it] = fA * 512 + SWZ(lane_a + 1) * 16 + regb * 4;
    }
    const int bN  = tid >> 2;
    const int bC2 = tid & 3;
    const int bKs = bC2 >> 1;
    const int bK0 = bKs * 16 + (bC2 & 1) * 4;
    const int bLane = (bN & 7) * 4 + (bC2 & 1) * 2;
    const int bDst = 16384 + ((bN >> 3) * 2 + bKs) * 256 + bLane * 8;
    const __half* bSrc = Bt + (size_t)(n0 + bN) * KDIM + bK0;

    float acc[4][4][4] = {};
    uint2 aLo[2], aHi[2], bLo, bHi;

    auto load_tile = [&](int kt) {
        #pragma unroll
        for (int it = 0; it < 2; it++) {
            int klocal = aC4[it] * 4;
            if (GATHER) {
                int kg = kt * 32 + klocal;
                int j = kg >> 8, c = kg & 255;
                int t = (aRow[it] >> 7) & 63;
                int tt = t + j - 1;
                aLo[it] = make_uint2(0, 0); aHi[it] = make_uint2(0, 0);
                if ((unsigned)tt < 64u) {
                    const __half* src = A + ((size_t)aRow[it] + (ptrdiff_t)(j - 1) * EE) * CC + c;
                    aLo[it] = *(const uint2*)src;
                    aHi[it] = *(const uint2*)(src + 8 * CC);
                }
            } else {
                const __half* src = A + (size_t)aRow[it] * KDIM + kt * 32 + klocal;
                aLo[it] = *(const uint2*)src;
                aHi[it] = *(const uint2*)(src + 8 * KDIM);
            }
        }
        bLo = *(const uint2*)(bSrc + kt * 32);
        bHi = *(const uint2*)(bSrc + kt * 32 + 8);
    };
    auto stage = [&](int buf) {
        char* s = smem + buf * 24576;
        #pragma unroll
        for (int it = 0; it < 2; it++) {
            *(uint2*)(s + aDst0[it]) = make_uint2(aLo[it].x, aHi[it].x);
            *(uint2*)(s + aDst1[it]) = make_uint2(aLo[it].y, aHi[it].y);
        }
        *(uint4*)(s + bDst) = make_uint4(bLo.x, bHi.x, bLo.y, bHi.y);
    };
    auto compute = [&](int buf) {
        const char* s = smem + buf * 24576;
        const int swl = SWZ(lane);
        #pragma unroll
        for (int ks = 0; ks < 2; ks++) {
            uint4 af[4];
            uint2 bf[4];
            #pragma unroll
            for (int mi = 0; mi < 4; mi++)
                af[mi] = *(const uint4*)(s + ((mg * 4 + mi) * 2 + ks) * 512 + swl * 16);
            #pragma unroll
            for (int ni = 0; ni < 4; ni++)
                bf[ni] = *(const uint2*)(s + 16384 + ((ng * 4 + ni) * 2 + ks) * 256 + lane * 8);
            #pragma unroll
            for (int mi = 0; mi < 4; mi++)
                #pragma unroll
                for (int ni = 0; ni < 4; ni++)
                    mma16(acc[mi][ni], af[mi], bf[ni]);
        }
    };

    load_tile(0);
    stage(0);
    __syncthreads();
    #pragma unroll 1
    for (int kt = 0; kt < NT; kt++) {
        if (kt + 1 < NT) load_tile(kt + 1);
        compute(kt & 1);
        if (kt + 1 < NT) {
            stage((kt + 1) & 1);
            __syncthreads();
        }
    }

    const float vm = vMul ? *vMul : 1.0f;
    #pragma unroll
    for (int mi = 0; mi < 4; mi++) {
        #pragma unroll
        for (int ni = 0; ni < 4; ni++) {
            int r0 = m0 + (mg * 4 + mi) * 16 + (lane >> 2);
            int c0 = n0 + (ng * 4 + ni) * 8 + 2 * (lane & 3);
            #pragma unroll
            for (int half = 0; half < 2; half++) {
                int row = r0 + half * 8;
                float v0 = acc[mi][ni][half * 2 + 0];
                float v1 = acc[mi][ni][half * 2 + 1];
                size_t base = (size_t)row * N + c0;
                if (colScale) {
                    v0 = v0 * colScale[c0] + colShift[c0];
                    v1 = v1 * colScale[c0 + 1] + colShift[c0 + 1];
                } else if (colShift) {
                    v0 += colShift[c0];
                    v1 += colShift[c0 + 1];
                }
                if (doGelu) { v0 = gelu_exact(v0); v1 = gelu_exact(v1); }
                if (res) {
                    float2 r2 = *(const float2*)(res + base);
                    v0 = resCoef * r2.x + vm * v0;
                    v1 = resCoef * r2.y + vm * v1;
                }
                if (OUTH) {
                    __half2 h2v = __floats2half2_rn(v0, v1);
                    *(__half2*)((__half*)Cv + base) = h2v;
                } else {
                    *(float2*)((float*)Cv + base) = make_float2(v0, v1);
                }
            }
        }
    }
}

// -------------------------------- launcher --------------------------------
template<typename T>
static T* symaddr(const void* sym)
{
    void* p = nullptr;
    cudaGetSymbolAddress(&p, sym);
    return (T*)p;
}

extern "C" void kernel_launch(void* const* d_in, const int* in_sizes, int n_in,
                              void* d_out, int out_size)
{
    const float* x       = (const float*)d_in[0];
    const int*   adj     = (const int*)  d_in[1];
    const float* n1_w    = (const float*)d_in[2];
    const float* n1_b    = (const float*)d_in[3];
    const float* q_w     = (const float*)d_in[4];
    const float* k_w     = (const float*)d_in[5];
    const float* v_w     = (const float*)d_in[6];
    const float* proj_w  = (const float*)d_in[7];
    const float* proj_b  = (const float*)d_in[8];
    const float* on_w    = (const float*)d_in[9];
    const float* on_b    = (const float*)d_in[10];
    const float* gamma_s = (const float*)d_in[11];
    const float* conv1_w = (const float*)d_in[12];
    const float* bn1_w   = (const float*)d_in[13];
    const float* bn1_b   = (const float*)d_in[14];
    const float* bn1_m   = (const float*)d_in[15];
    const float* bn1_v   = (const float*)d_in[16];
    const float* conv2_w = (const float*)d_in[17];
    const float* bn2_w   = (const float*)d_in[18];
    const float* bn2_b   = (const float*)d_in[19];
    const float* bn2_m   = (const float*)d_in[20];
    const float* bn2_v   = (const float*)d_in[21];
    const float* tn_w    = (const float*)d_in[22];
    const float* tn_b    = (const float*)d_in[23];
    const float* gamma_t = (const float*)d_in[24];
    const float* n3_w    = (const float*)d_in[25];
    const float* n3_b    = (const float*)d_in[26];
    const float* fc1_w   = (const float*)d_in[27];
    const float* fc1_b   = (const float*)d_in[28];
    const float* fc2_w   = (const float*)d_in[29];
    const float* fc2_b   = (const float*)d_in[30];
    float* out = (float*)d_out;

    float*  xs   = symaddr<float >(g_xs);
    __half* xs16 = symaddr<__half>(g_xs16);
    __half* qkvh = symaddr<__half>(g_qkvh);
    __half* o16  = symaddr<__half>(g_o16);
    float*  p    = symaddr<float >(g_p);
    float*  x1   = symaddr<float >(g_x1);
    __half* xt16 = symaddr<__half>(g_xt16);
    __half* y1h  = symaddr<__half>(g_y1h);
    float*  x2   = symaddr<float >(g_x2);
    __half* xm16 = symaddr<__half>(g_xm16);
    __half* bigh = symaddr<__half>(g_bigh);
    __half* hqkv = symaddr<__half>(g_hqkv);
    __half* hp   = symaddr<__half>(g_hp);
    __half* hw1  = symaddr<__half>(g_hw1);
    __half* hw2  = symaddr<__half>(g_hw2);
    __half* hf1  = symaddr<__half>(g_hf1);
    __half* hf2  = symaddr<__half>(g_hf2);
    float* bn1s = symaddr<float>(g_bn1s);
    float* bn1b = symaddr<float>(g_bn1b);
    float* bn2s = symaddr<float>(g_bn2s);
    float* bn2b = symaddr<float>(g_bn2b);

    cudaFuncSetAttribute(h_gemm<256,  false, true >, cudaFuncAttributeMaxDynamicSharedMemorySize, HG_SMEM);
    cudaFuncSetAttribute(h_gemm<256,  false, false>, cudaFuncAttributeMaxDynamicSharedMemorySize, HG_SMEM);
    cudaFuncSetAttribute(h_gemm<768,  true,  true >, cudaFuncAttributeMaxDynamicSharedMemorySize, HG_SMEM);
    cudaFuncSetAttribute(h_gemm<512,  false, false>, cudaFuncAttributeMaxDynamicSharedMemorySize, HG_SMEM);
    cudaFuncSetAttribute(h_gemm<1024, false, false>, cudaFuncAttributeMaxDynamicSharedMemorySize, HG_SMEM);
    cudaFuncSetAttribute(attn_mma, cudaFuncAttributeMaxDynamicSharedMemorySize, ATT_SMEM);

    // 0) prep: fp16 weight transposes + BN folding + mask
    prep_kernel<<<1536, 256>>>(q_w, k_w, v_w, proj_w, conv1_w, conv2_w, fc1_w, fc2_w, adj,
                               bn1_w, bn1_b, bn1_m, bn1_v,
                               bn2_w, bn2_b, bn2_m, bn2_v);

    // 1) xs = LN(x)  (fp32 + fp16)
    ln_dual_kernel<<<RROWS, 256>>>(x, n1_w, n1_b, xs, xs16);

    // 2) fused QKV GEMM -> [R][768] fp16
    h_gemm<256, false, true><<<dim3(6, 256), 512, HG_SMEM>>>(xs16, hqkv, qkvh, 768,
        nullptr, nullptr, 0, nullptr, 0.f, nullptr);

    // 3) tensor-core masked attention -> o16
    attn_mma<<<BB * TT, 256, ATT_SMEM>>>(qkvh, o16);

    // 4) proj: P = o @ proj_w + proj_b
    h_gemm<256, false, false><<<dim3(2, 256), 512, HG_SMEM>>>(o16, hp, p, CC,
        nullptr, proj_b, 0, nullptr, 0.f, nullptr);

    // 5) x1 = x + xs + gamma_s*LN(P)
    lnres_kernel<<<RROWS, 256>>>(p, x, xs, on_w, on_b, gamma_s, x1);

    // 6) xt = LN(x1) fp16
    ln_h_kernel<<<RROWS, 256>>>(x1, tn_w, tn_b, xt16);

    // 7) conv1 (gathered) + BN1 + GELU -> y1 fp16
    h_gemm<768, true, true><<<dim3(4, 256), 512, HG_SMEM>>>(xt16, hw1, y1h, HH2,
        bn1s, bn1b, 1, nullptr, 0.f, nullptr);

    // 8) conv2 + BN2, x2 = 2*x1 + gamma_t*y
    h_gemm<512, false, false><<<dim3(2, 256), 512, HG_SMEM>>>(y1h, hw2, x2, CC,
        bn2s, bn2b, 0, x1, 2.0f, gamma_t);

    // 9) xm = LN(x2) fp16
    ln_h_kernel<<<RROWS, 256>>>(x2, n3_w, n3_b, xm16);

    // 10) fc1 + bias + GELU -> big fp16
    h_gemm<256, false, true><<<dim3(8, 256), 512, HG_SMEM>>>(xm16, hf1, bigh, MM,
        nullptr, fc1_b, 1, nullptr, 0.f, nullptr);

    // 11) fc2 + bias + residual x2 -> out fp32
    h_gemm<1024, false, false><<<dim3(2, 256), 512, HG_SMEM>>>(bigh, hf2, out, CC,
        nullptr, fc2_b, 0, x2, 1.0f, nullptr);
}

// round 6
// speedup vs baseline: 4.5063x; 1.0382x over previous
#include <cuda_runtime.h>
#include <cuda_fp16.h>
#include <cstdint>
#include <math.h>

// ---------------- problem constants ----------------
#define BB 8
#define TT 64
#define EE 128
#define CC 256
#define HH2 512          // conv hidden
#define MM 1024          // mlp hidden
#define RROWS 65536      // B*T*E
#define LNEPS 1e-5f

// ---------------- device scratch ----------------
__device__ __align__(128) float  g_xs  [RROWS * CC];    // xs fp32 (residual use)
__device__ __align__(128) __half g_xs16[RROWS * CC];    // xs fp16 (GEMM A)
__device__ __align__(128) __half g_qkvh[RROWS * 768];   // q|k|v fp16
__device__ __align__(128) __half g_o16 [RROWS * CC];    // attn out fp16
__device__ __align__(128) float  g_p   [RROWS * CC];    // proj out fp32
__device__ __align__(128) float  g_x1  [RROWS * CC];    // x1 fp32
__device__ __align__(128) __half g_xt16[RROWS * CC];    // LN(x1) fp16
__device__ __align__(128) __half g_y1h [RROWS * HH2];   // conv1 out fp16
__device__ __align__(128) float  g_x2  [RROWS * CC];    // x2 fp32
__device__ __align__(128) __half g_xm16[RROWS * CC];    // LN(x2) fp16
__device__ __align__(128) __half g_bigh[RROWS * MM];    // mlp hidden fp16
// fp16 weights, all [N][K] K-major
__device__ __align__(128) __half g_hqkv[768 * CC];
__device__ __align__(128) __half g_hp  [CC * CC];
__device__ __align__(128) __half g_hw1 [HH2 * 768];     // conv1: [h][kk], kk=j*256+c
__device__ __align__(128) __half g_hw2 [CC * HH2];
__device__ __align__(128) __half g_hf1 [MM * CC];
__device__ __align__(128) __half g_hf2 [CC * MM];
__device__ __align__(128) float g_maskf[EE * EE];       // 0.5 * adj_mask
__device__ __align__(128) float g_bn1s[HH2], g_bn1b[HH2], g_bn2s[CC], g_bn2b[CC];

// ---------------- helpers ----------------
#define SWZ(l) ((l) ^ ((l) >> 3))

__device__ __forceinline__ void mma16(float* d, const uint4& a, const uint2& b)
{
    asm volatile("mma.sync.aligned.m16n8k16.row.col.f32.f16.f16.f32 "
                 "{%0,%1,%2,%3}, {%4,%5,%6,%7}, {%8,%9}, {%0,%1,%2,%3};"
                 : "+f"(d[0]), "+f"(d[1]), "+f"(d[2]), "+f"(d[3])
                 : "r"(a.x), "r"(a.y), "r"(a.z), "r"(a.w), "r"(b.x), "r"(b.y));
}

__device__ __forceinline__ float gelu_exact(float v)
{
    return 0.5f * v * (1.f + erff(v * 0.70710678118654752f));
}

// ---------------- prep ----------------
__global__ void prep_kernel(const float* __restrict__ qw, const float* __restrict__ kw,
                            const float* __restrict__ vw, const float* __restrict__ pw,
                            const float* __restrict__ w1, const float* __restrict__ w2,
                            const float* __restrict__ f1, const float* __restrict__ f2,
                            const int* __restrict__ mask,
                            const float* __restrict__ b1w, const float* __restrict__ b1b,
                            const float* __restrict__ b1m, const float* __restrict__ b1v,
                            const float* __restrict__ b2w, const float* __restrict__ b2b,
                            const float* __restrict__ b2m, const float* __restrict__ b2v)
{
    int idx = blockIdx.x * blockDim.x + threadIdx.x;
    if (idx < 768 * CC) {           // qkv concat [n][k]
        int n = idx >> 8, k = idx & 255;
        const float* src = (n < 256) ? qw : (n < 512) ? kw : vw;
        g_hqkv[idx] = __float2half(src[k * CC + (n & 255)]);
    }
    if (idx < CC * CC) {
        int n = idx >> 8, k = idx & 255;
        g_hp[idx] = __float2half(pw[k * CC + n]);
    }
    if (idx < HH2 * 768) {
        int h = idx / 768, kk = idx % 768;
        int j = kk >> 8, c = kk & 255;
        g_hw1[idx] = __float2half(w1[h * 768 + c * 3 + j]);
    }
    if (idx < CC * HH2) g_hw2[idx] = __float2half(w2[idx]);   // already [c][h]
    if (idx < MM * CC) {
        int n = idx >> 8, k = idx & 255;
        g_hf1[idx] = __float2half(f1[k * MM + n]);
    }
    if (idx < CC * MM) {
        int n = idx >> 10, k = idx & 1023;
        g_hf2[idx] = __float2half(f2[k * CC + n]);
    }
    if (idx < EE * EE) g_maskf[idx] = 0.5f * (float)mask[idx];
    if (idx < HH2) {
        float s = b1w[idx] * rsqrtf(b1v[idx] + LNEPS);
        g_bn1s[idx] = s;
        g_bn1b[idx] = b1b[idx] - b1m[idx] * s;
    }
    if (idx < CC) {
        float s = b2w[idx] * rsqrtf(b2v[idx] + LNEPS);
        g_bn2s[idx] = s;
        g_bn2b[idx] = b2b[idx] - b2m[idx] * s;
    }
}

// ---------------- row reduce (mean, rstd) ----------------
__device__ __forceinline__ void row_stats(float v, int tid, float& mean, float& rstd)
{
    __shared__ float sa[8], sb[8];
    __syncthreads();                 // guard smem reuse across repeated calls
    float s = v, s2 = v * v;
    #pragma unroll
    for (int o = 16; o; o >>= 1) {
        s  += __shfl_down_sync(0xffffffffu, s,  o);
        s2 += __shfl_down_sync(0xffffffffu, s2, o);
    }
    int lane = tid & 31, wid = tid >> 5;
    if (!lane) { sa[wid] = s; sb[wid] = s2; }
    __syncthreads();
    if (tid < 32) {
        s  = (tid < 8) ? sa[tid] : 0.f;
        s2 = (tid < 8) ? sb[tid] : 0.f;
        #pragma unroll
        for (int o = 4; o; o >>= 1) {
            s  += __shfl_down_sync(0xffffffffu, s,  o);
            s2 += __shfl_down_sync(0xffffffffu, s2, o);
        }
        if (!tid) {
            float m = s * (1.f / CC);
            sa[0] = m;
            sb[0] = rsqrtf(s2 * (1.f / CC) - m * m + LNEPS);
        }
    }
    __syncthreads();
    mean = sa[0]; rstd = sb[0];
}

__global__ void ln_dual_kernel(const float* __restrict__ in, const float* __restrict__ w,
                               const float* __restrict__ b, float* __restrict__ o32,
                               __half* __restrict__ o16)
{
    int tid = threadIdx.x;
    size_t idx = (size_t)blockIdx.x * CC + tid;
    float v = in[idx];
    float mean, rstd;
    row_stats(v, tid, mean, rstd);
    float r = (v - mean) * rstd * w[tid] + b[tid];
    o32[idx] = r;
    o16[idx] = __float2half(r);
}

__global__ void ln_h_kernel(const float* __restrict__ in, const float* __restrict__ w,
                            const float* __restrict__ b, __half* __restrict__ o16)
{
    int tid = threadIdx.x;
    size_t idx = (size_t)blockIdx.x * CC + tid;
    float v = in[idx];
    float mean, rstd;
    row_stats(v, tid, mean, rstd);
    o16[idx] = __float2half((v - mean) * rstd * w[tid] + b[tid]);
}

// fused: x1 = x + xs + gamma_s*LN(P); xt16 = LN(x1)
__global__ void lnres_ln_kernel(const float* __restrict__ P, const float* __restrict__ x,
                                const float* __restrict__ xs, const float* __restrict__ ow,
                                const float* __restrict__ ob, const float* __restrict__ gamma,
                                const float* __restrict__ tw, const float* __restrict__ tb,
                                float* __restrict__ x1, __half* __restrict__ xt16)
{
    int tid = threadIdx.x;
    size_t idx = (size_t)blockIdx.x * CC + tid;
    float v = P[idx];
    float mean, rstd;
    row_stats(v, tid, mean, rstd);
    float ln = (v - mean) * rstd * ow[tid] + ob[tid];
    float xv = x[idx] + xs[idx] + gamma[0] * ln;
    x1[idx] = xv;
    float mean2, rstd2;
    row_stats(xv, tid, mean2, rstd2);
    xt16[idx] = __float2half((xv - mean2) * rstd2 * tw[tid] + tb[tid]);
}

// ---------------- tensor-core attention: CTA per (b,t), 8 warps, loop heads ----
#define MSTR 136
#define QSTR 40
#define VSTR 136
static constexpr int ATT_SMEM = 64000;

__global__ void __launch_bounds__(256, 2) attn_mma(const __half* __restrict__ QKV,
                                                   __half* __restrict__ O)
{
    extern __shared__ __align__(128) __half sm[];
    __half* maskS = sm;                  // [128][MSTR]
    __half* Qs = sm + 17408;             // [128][QSTR]
    __half* Ks = Qs + 5120;
    __half* Vt = Ks + 5120;              // [32][VSTR]
    const int tid = threadIdx.x, w = tid >> 5, lane = tid & 31;
    const int bt = blockIdx.x;
    const int r = lane >> 2, c = lane & 3;
    const int eBase = w * 16;

    for (int i = tid; i < 128 * 32; i += 256) {
        int e = i >> 5, f4 = (i & 31) * 4;
        float4 mv = *(const float4*)&g_maskf[e * 128 + f4];
        __half2 h0 = __floats2half2_rn(mv.x, mv.y);
        __half2 h1 = __floats2half2_rn(mv.z, mv.w);
        *(uint2*)&maskS[e * MSTR + f4] = make_uint2(*(uint32_t*)&h0, *(uint32_t*)&h1);
    }
    __syncthreads();

    const __half* qbase = QKV + (size_t)bt * 128 * 768;
    const int se = tid >> 1, sp = tid & 1;

    for (int h = 0; h < 8; h++) {
        {
            const __half* row = qbase + (size_t)se * 768 + h * 32 + sp * 16;
            uint4 q0 = *(const uint4*)(row);
            uint4 q1 = *(const uint4*)(row + 8);
            *(uint4*)&Qs[se * QSTR + sp * 16]     = q0;
            *(uint4*)&Qs[se * QSTR + sp * 16 + 8] = q1;
            uint4 k0 = *(const uint4*)(row + 256);
            uint4 k1 = *(const uint4*)(row + 264);
            *(uint4*)&Ks[se * QSTR + sp * 16]     = k0;
            *(uint4*)&Ks[se * QSTR + sp * 16 + 8] = k1;
            uint4 v0 = *(const uint4*)(row + 512);
            uint4 v1 = *(const uint4*)(row + 520);
            const __half* vh0 = (const __half*)&v0;
            const __half* vh1 = (const __half*)&v1;
            #pragma unroll
            for (int i = 0; i < 8; i++) {
                Vt[(sp * 16 + i) * VSTR + se]     = vh0[i];
                Vt[(sp * 16 + 8 + i) * VSTR + se] = vh1[i];
            }
        }
        __syncthreads();

        uint4 aQ[2];
        #pragma unroll
        for (int ks = 0; ks < 2; ks++) {
            const __half* q0 = &Qs[(eBase + r) * QSTR + ks * 16 + 2 * c];
            aQ[ks].x = *(const uint32_t*)q0;
            aQ[ks].y = *(const uint32_t*)(q0 + 8 * QSTR);
            aQ[ks].z = *(const uint32_t*)(q0 + 8);
            aQ[ks].w = *(const uint32_t*)(q0 + 8 * QSTR + 8);
        }

        float oacc[4][4] = {};
        #pragma unroll
        for (int ph = 0; ph < 2; ph++) {
            float sacc[8][4] = {};
            #pragma unroll
            for (int nt = 0; nt < 8; nt++) {
                const __half* kp = &Ks[(ph * 64 + nt * 8 + r) * QSTR + 2 * c];
                #pragma unroll
                for (int ks = 0; ks < 2; ks++) {
                    uint2 bf;
                    bf.x = *(const uint32_t*)(kp + ks * 16);
                    bf.y = *(const uint32_t*)(kp + ks * 16 + 8);
                    mma16(sacc[nt], aQ[ks], bf);
                }
            }
            uint32_t wh[8][2];
            #pragma unroll
            for (int nt = 0; nt < 8; nt++) {
                int fb = ph * 64 + nt * 8 + 2 * c;
                float2 m0 = __half22float2(*(__half2*)&maskS[(eBase + r) * MSTR + fb]);
                float2 m1 = __half22float2(*(__half2*)&maskS[(eBase + r + 8) * MSTR + fb]);
                __half2 w0 = __floats2half2_rn(sacc[nt][0] * m0.x + 0.5f,
                                               sacc[nt][1] * m0.y + 0.5f);
                __half2 w1 = __floats2half2_rn(sacc[nt][2] * m1.x + 0.5f,
                                               sacc[nt][3] * m1.y + 0.5f);
                wh[nt][0] = *(uint32_t*)&w0;
                wh[nt][1] = *(uint32_t*)&w1;
            }
            #pragma unroll
            for (int kk = 0; kk < 4; kk++) {
                uint4 aw = make_uint4(wh[2 * kk][0], wh[2 * kk][1],
                                      wh[2 * kk + 1][0], wh[2 * kk + 1][1]);
                #pragma unroll
                for (int dt = 0; dt < 4; dt++) {
                    const __half* vp = &Vt[(dt * 8 + r) * VSTR + ph * 64 + kk * 16 + 2 * c];
                    uint2 bf;
                    bf.x = *(const uint32_t*)vp;
                    bf.y = *(const uint32_t*)(vp + 8);
                    mma16(oacc[dt], aw, bf);
                }
            }
        }
        size_t ob = ((size_t)bt * 128 + eBase + r) * 256 + h * 32;
        #pragma unroll
        for (int dt = 0; dt < 4; dt++) {
            __half2 o0 = __floats2half2_rn(oacc[dt][0], oacc[dt][1]);
            __half2 o1 = __floats2half2_rn(oacc[dt][2], oacc[dt][3]);
            *(uint32_t*)&O[ob + dt * 8 + 2 * c]           = *(uint32_t*)&o0;
            *(uint32_t*)&O[ob + 8 * 256 + dt * 8 + 2 * c] = *(uint32_t*)&o1;
        }
        __syncthreads();
    }
}

// ---------------- fp16 mma GEMM: CTA 128x128, 256 threads, 2m x 4n warps -------
// 2 CTAs/SM (32KB smem, <=128 regs) to overlap staging/sync bubbles across CTAs.
static constexpr int HG_SMEM = 32768;

template<int KDIM, bool GATHER, bool OUTH>
__global__ void __launch_bounds__(256, 2) h_gemm(
        const __half* __restrict__ A, const __half* __restrict__ Bt,
        void* __restrict__ Cv, int N,
        const float* __restrict__ colScale, const float* __restrict__ colShift,
        int doGelu, const float* __restrict__ res, float resCoef,
        const float* __restrict__ vMul)
{
    extern __shared__ __align__(128) char smem[];
    constexpr int NT = KDIM / 32;
    const int tid = threadIdx.x;
    const int w = tid >> 5, lane = tid & 31;
    const int n0 = blockIdx.x * 128, m0 = blockIdx.y * 128;
    const int mg = w >> 2, ng = w & 3;

    // A staging: 2 items/thread over id in [0,512): 128 rows x 4 col-chunks x ks
    int aC4[2], aDst0[2], aDst1[2], aRow[2];
    #pragma unroll
    for (int it = 0; it < 2; it++) {
        int id = tid + it * 256;
        int mi = id >> 6, rl = (id >> 3) & 7, c4 = id & 7;
        int ks = c4 >> 2;
        int lane_a = rl * 4 + (c4 & 1) * 2;
        int regb = 2 * ((c4 & 3) >> 1);
        int fA = mi * 2 + ks;
        aC4[it] = c4;
        aRow[it] = m0 + mi * 16 + rl;
        aDst0[it] = fA * 512 + SWZ(lane_a) * 16 + regb * 4;
        aDst1[it] = fA * 512 + SWZ(lane_a + 1) * 16 + regb * 4;
    }
    // B staging: 2 items/thread over id in [0,512): 128 n-rows x 4 k-chunks
    int bDst[2];
    const __half* bSrc[2];
    #pragma unroll
    for (int it = 0; it < 2; it++) {
        int id = tid + it * 256;
        int bN = id >> 2, bC2 = id & 3;
        int bKs = bC2 >> 1;
        int bK0 = bKs * 16 + (bC2 & 1) * 4;
        int bLane = (bN & 7) * 4 + (bC2 & 1) * 2;
        bDst[it] = 8192 + ((bN >> 3) * 2 + bKs) * 256 + bLane * 8;
        bSrc[it] = Bt + (size_t)(n0 + bN) * KDIM + bK0;
    }

    float acc[4][4][4] = {};
    uint2 aLo[2], aHi[2], bLo[2], bHi[2];

    auto load_tile = [&](int kt) {
        #pragma unroll
        for (int it = 0; it < 2; it++) {
            int klocal = aC4[it] * 4;
            if (GATHER) {
                int kg = kt * 32 + klocal;
                int j = kg >> 8, c = kg & 255;
                int t = (aRow[it] >> 7) & 63;
                int tt = t + j - 1;
                aLo[it] = make_uint2(0, 0); aHi[it] = make_uint2(0, 0);
                if ((unsigned)tt < 64u) {
                    const __half* src = A + ((size_t)aRow[it] + (ptrdiff_t)(j - 1) * EE) * CC + c;
                    aLo[it] = *(const uint2*)src;
                    aHi[it] = *(const uint2*)(src + 8 * CC);
                }
            } else {
                const __half* src = A + (size_t)aRow[it] * KDIM + kt * 32 + klocal;
                aLo[it] = *(const uint2*)src;
                aHi[it] = *(const uint2*)(src + 8 * KDIM);
            }
            bLo[it] = *(const uint2*)(bSrc[it] + kt * 32);
            bHi[it] = *(const uint2*)(bSrc[it] + kt * 32 + 8);
        }
    };
    auto stage = [&](int buf) {
        char* s = smem + buf * 16384;
        #pragma unroll
        for (int it = 0; it < 2; it++) {
            *(uint2*)(s + aDst0[it]) = make_uint2(aLo[it].x, aHi[it].x);
            *(uint2*)(s + aDst1[it]) = make_uint2(aLo[it].y, aHi[it].y);
            *(uint4*)(s + bDst[it]) = make_uint4(bLo[it].x, bHi[it].x, bLo[it].y, bHi[it].y);
        }
    };
    auto compute = [&](int buf) {
        const char* s = smem + buf * 16384;
        const int swl = SWZ(lane);
        #pragma unroll
        for (int ks = 0; ks < 2; ks++) {
            uint4 af[4];
            uint2 bf[4];
            #pragma unroll
            for (int mi = 0; mi < 4; mi++)
                af[mi] = *(const uint4*)(s + ((mg * 4 + mi) * 2 + ks) * 512 + swl * 16);
            #pragma unroll
            for (int ni = 0; ni < 4; ni++)
                bf[ni] = *(const uint2*)(s + 8192 + ((ng * 4 + ni) * 2 + ks) * 256 + lane * 8);
            #pragma unroll
            for (int mi = 0; mi < 4; mi++)
                #pragma unroll
                for (int ni = 0; ni < 4; ni++)
                    mma16(acc[mi][ni], af[mi], bf[ni]);
        }
    };

    load_tile(0);
    stage(0);
    __syncthreads();
    #pragma unroll 1
    for (int kt = 0; kt < NT; kt++) {
        if (kt + 1 < NT) load_tile(kt + 1);
        compute(kt & 1);
        if (kt + 1 < NT) {
            __syncthreads();
            stage((kt + 1) & 1);
            __syncthreads();
        }
    }

    const float vm = vMul ? *vMul : 1.0f;
    #pragma unroll
    for (int mi = 0; mi < 4; mi++) {
        #pragma unroll
        for (int ni = 0; ni < 4; ni++) {
            int r0 = m0 + (mg * 4 + mi) * 16 + (lane >> 2);
            int c0 = n0 + (ng * 4 + ni) * 8 + 2 * (lane & 3);
            #pragma unroll
            for (int half = 0; half < 2; half++) {
                int row = r0 + half * 8;
                float v0 = acc[mi][ni][half * 2 + 0];
                float v1 = acc[mi][ni][half * 2 + 1];
                size_t base = (size_t)row * N + c0;
                if (colScale) {
                    v0 = v0 * colScale[c0] + colShift[c0];
                    v1 = v1 * colScale[c0 + 1] + colShift[c0 + 1];
                } else if (colShift) {
                    v0 += colShift[c0];
                    v1 += colShift[c0 + 1];
                }
                if (doGelu) { v0 = gelu_exact(v0); v1 = gelu_exact(v1); }
                if (res) {
                    float2 r2 = *(const float2*)(res + base);
                    v0 = resCoef * r2.x + vm * v0;
                    v1 = resCoef * r2.y + vm * v1;
                }
                if (OUTH) {
                    __half2 h2v = __floats2half2_rn(v0, v1);
                    *(__half2*)((__half*)Cv + base) = h2v;
                } else {
                    *(float2*)((float*)Cv + base) = make_float2(v0, v1);
                }
            }
        }
    }
}

// -------------------------------- launcher --------------------------------
template<typename T>
static T* symaddr(const void* sym)
{
    void* p = nullptr;
    cudaGetSymbolAddress(&p, sym);
    return (T*)p;
}

extern "C" void kernel_launch(void* const* d_in, const int* in_sizes, int n_in,
                              void* d_out, int out_size)
{
    const float* x       = (const float*)d_in[0];
    const int*   adj     = (const int*)  d_in[1];
    const float* n1_w    = (const float*)d_in[2];
    const float* n1_b    = (const float*)d_in[3];
    const float* q_w     = (const float*)d_in[4];
    const float* k_w     = (const float*)d_in[5];
    const float* v_w     = (const float*)d_in[6];
    const float* proj_w  = (const float*)d_in[7];
    const float* proj_b  = (const float*)d_in[8];
    const float* on_w    = (const float*)d_in[9];
    const float* on_b    = (const float*)d_in[10];
    const float* gamma_s = (const float*)d_in[11];
    const float* conv1_w = (const float*)d_in[12];
    const float* bn1_w   = (const float*)d_in[13];
    const float* bn1_b   = (const float*)d_in[14];
    const float* bn1_m   = (const float*)d_in[15];
    const float* bn1_v   = (const float*)d_in[16];
    const float* conv2_w = (const float*)d_in[17];
    const float* bn2_w   = (const float*)d_in[18];
    const float* bn2_b   = (const float*)d_in[19];
    const float* bn2_m   = (const float*)d_in[20];
    const float* bn2_v   = (const float*)d_in[21];
    const float* tn_w    = (const float*)d_in[22];
    const float* tn_b    = (const float*)d_in[23];
    const float* gamma_t = (const float*)d_in[24];
    const float* n3_w    = (const float*)d_in[25];
    const float* n3_b    = (const float*)d_in[26];
    const float* fc1_w   = (const float*)d_in[27];
    const float* fc1_b   = (const float*)d_in[28];
    const float* fc2_w   = (const float*)d_in[29];
    const float* fc2_b   = (const float*)d_in[30];
    float* out = (float*)d_out;

    float*  xs   = symaddr<float >(g_xs);
    __half* xs16 = symaddr<__half>(g_xs16);
    __half* qkvh = symaddr<__half>(g_qkvh);
    __half* o16  = symaddr<__half>(g_o16);
    float*  p    = symaddr<float >(g_p);
    float*  x1   = symaddr<float >(g_x1);
    __half* xt16 = symaddr<__half>(g_xt16);
    __half* y1h  = symaddr<__half>(g_y1h);
    float*  x2   = symaddr<float >(g_x2);
    __half* xm16 = symaddr<__half>(g_xm16);
    __half* bigh = symaddr<__half>(g_bigh);
    __half* hqkv = symaddr<__half>(g_hqkv);
    __half* hp   = symaddr<__half>(g_hp);
    __half* hw1  = symaddr<__half>(g_hw1);
    __half* hw2  = symaddr<__half>(g_hw2);
    __half* hf1  = symaddr<__half>(g_hf1);
    __half* hf2  = symaddr<__half>(g_hf2);
    float* bn1s = symaddr<float>(g_bn1s);
    float* bn1b = symaddr<float>(g_bn1b);
    float* bn2s = symaddr<float>(g_bn2s);
    float* bn2b = symaddr<float>(g_bn2b);

    cudaFuncSetAttribute(attn_mma, cudaFuncAttributeMaxDynamicSharedMemorySize, ATT_SMEM);

    // 0) prep: fp16 weight transposes + BN folding + mask
    prep_kernel<<<1536, 256>>>(q_w, k_w, v_w, proj_w, conv1_w, conv2_w, fc1_w, fc2_w, adj,
                               bn1_w, bn1_b, bn1_m, bn1_v,
                               bn2_w, bn2_b, bn2_m, bn2_v);

    // 1) xs = LN(x)  (fp32 + fp16)
    ln_dual_kernel<<<RROWS, 256>>>(x, n1_w, n1_b, xs, xs16);

    // 2) fused QKV GEMM -> [R][768] fp16
    h_gemm<256, false, true><<<dim3(6, 512), 256, HG_SMEM>>>(xs16, hqkv, qkvh, 768,
        nullptr, nullptr, 0, nullptr, 0.f, nullptr);

    // 3) tensor-core masked attention -> o16
    attn_mma<<<BB * TT, 256, ATT_SMEM>>>(qkvh, o16);

    // 4) proj: P = o @ proj_w + proj_b
    h_gemm<256, false, false><<<dim3(2, 512), 256, HG_SMEM>>>(o16, hp, p, CC,
        nullptr, proj_b, 0, nullptr, 0.f, nullptr);

    // 5+6) x1 = x + xs + gamma_s*LN(P);  xt16 = LN(x1)
    lnres_ln_kernel<<<RROWS, 256>>>(p, x, xs, on_w, on_b, gamma_s, tn_w, tn_b, x1, xt16);

    // 7) conv1 (gathered) + BN1 + GELU -> y1 fp16
    h_gemm<768, true, true><<<dim3(4, 512), 256, HG_SMEM>>>(xt16, hw1, y1h, HH2,
        bn1s, bn1b, 1, nullptr, 0.f, nullptr);

    // 8) conv2 + BN2, x2 = 2*x1 + gamma_t*y
    h_gemm<512, false, false><<<dim3(2, 512), 256, HG_SMEM>>>(y1h, hw2, x2, CC,
        bn2s, bn2b, 0, x1, 2.0f, gamma_t);

    // 9) xm = LN(x2) fp16
    ln_h_kernel<<<RROWS, 256>>>(x2, n3_w, n3_b, xm16);

    // 10) fc1 + bias + GELU -> big fp16
    h_gemm<256, false, true><<<dim3(8, 512), 256, HG_SMEM>>>(xm16, hf1, bigh, MM,
        nullptr, fc1_b, 1, nullptr, 0.f, nullptr);

    // 11) fc2 + bias + residual x2 -> out fp32
    h_gemm<1024, false, false><<<dim3(2, 512), 256, HG_SMEM>>>(bigh, hf2, out, CC,
        nullptr, fc2_b, 0, x2, 1.0f, nullptr);
}

// round 7
// speedup vs baseline: 5.5110x; 1.2229x over previous
#include <cuda_runtime.h>
#include <cuda_fp16.h>
#include <cstdint>
#include <math.h>

// ---------------- problem constants ----------------
#define BB 8
#define TT 64
#define EE 128
#define CC 256
#define HH2 512          // conv hidden
#define MM 1024          // mlp hidden
#define RROWS 65536      // B*T*E
#define LNEPS 1e-5f

// ---------------- device scratch ----------------
__device__ __align__(128) __half g_xs16[RROWS * CC];    // xs fp16
__device__ __align__(128) __half g_qkvh[RROWS * 768];   // q|k|v fp16
__device__ __align__(128) __half g_o16 [RROWS * CC];    // attn out fp16
__device__ __align__(128) float  g_p   [RROWS * CC];    // proj out fp32
__device__ __align__(128) float  g_x1  [RROWS * CC];    // x1 fp32
__device__ __align__(128) __half g_xt16[RROWS * CC];    // LN(x1) fp16
__device__ __align__(128) __half g_y1h [RROWS * HH2];   // conv1 out fp16
__device__ __align__(128) float  g_x2  [RROWS * CC];    // x2 fp32
__device__ __align__(128) __half g_xm16[RROWS * CC];    // LN(x2) fp16
__device__ __align__(128) __half g_bigh[RROWS * MM];    // mlp hidden fp16
// fp16 weights, all [N][K] K-major
__device__ __align__(128) __half g_hqkv[768 * CC];
__device__ __align__(128) __half g_hp  [CC * CC];
__device__ __align__(128) __half g_hw1 [HH2 * 768];     // conv1: [h][kk], kk=j*256+c
__device__ __align__(128) __half g_hw2 [CC * HH2];
__device__ __align__(128) __half g_hf1 [MM * CC];
__device__ __align__(128) __half g_hf2 [CC * MM];
__device__ __align__(128) float g_maskf[EE * EE];       // 0.5 * adj_mask
__device__ __align__(128) float g_bn1s[HH2], g_bn1b[HH2], g_bn2s[CC], g_bn2b[CC];

// ---------------- helpers ----------------
__device__ __forceinline__ uint32_t smem_u32(const void* p)
{
    uint32_t a;
    asm("{ .reg .u64 t; cvta.to.shared.u64 t, %1; cvt.u32.u64 %0, t; }" : "=r"(a) : "l"(p));
    return a;
}
__device__ __forceinline__ void mma16(float* d, const uint4& a, const uint2& b)
{
    asm volatile("mma.sync.aligned.m16n8k16.row.col.f32.f16.f16.f32 "
                 "{%0,%1,%2,%3}, {%4,%5,%6,%7}, {%8,%9}, {%0,%1,%2,%3};"
                 : "+f"(d[0]), "+f"(d[1]), "+f"(d[2]), "+f"(d[3])
                 : "r"(a.x), "r"(a.y), "r"(a.z), "r"(a.w), "r"(b.x), "r"(b.y));
}
__device__ __forceinline__ uint4 ldsm4(uint32_t addr)
{
    uint4 r;
    asm volatile("ldmatrix.sync.aligned.m8n8.x4.shared.b16 {%0,%1,%2,%3}, [%4];"
                 : "=r"(r.x), "=r"(r.y), "=r"(r.z), "=r"(r.w) : "r"(addr));
    return r;
}
__device__ __forceinline__ uint2 ldsm2(uint32_t addr)
{
    uint2 r;
    asm volatile("ldmatrix.sync.aligned.m8n8.x2.shared.b16 {%0,%1}, [%2];"
                 : "=r"(r.x), "=r"(r.y) : "r"(addr));
    return r;
}
__device__ __forceinline__ void cpa16(uint32_t dst, const void* src)
{
    asm volatile("cp.async.cg.shared.global [%0], [%1], 16;" :: "r"(dst), "l"(src));
}
__device__ __forceinline__ void cpa16z(uint32_t dst, const void* src, int srcsize)
{
    asm volatile("cp.async.cg.shared.global [%0], [%1], 16, %2;"
                 :: "r"(dst), "l"(src), "r"(srcsize));
}
#define CP_COMMIT() asm volatile("cp.async.commit_group;" ::: "memory")
#define CP_WAIT2()  asm volatile("cp.async.wait_group 2;" ::: "memory")

__device__ __forceinline__ float gelu_exact(float v)
{
    return 0.5f * v * (1.f + erff(v * 0.70710678118654752f));
}

// ---------------- prep ----------------
__global__ void prep_kernel(const float* __restrict__ qw, const float* __restrict__ kw,
                            const float* __restrict__ vw, const float* __restrict__ pw,
                            const float* __restrict__ w1, const float* __restrict__ w2,
                            const float* __restrict__ f1, const float* __restrict__ f2,
                            const int* __restrict__ mask,
                            const float* __restrict__ b1w, const float* __restrict__ b1b,
                            const float* __restrict__ b1m, const float* __restrict__ b1v,
                            const float* __restrict__ b2w, const float* __restrict__ b2b,
                            const float* __restrict__ b2m, const float* __restrict__ b2v)
{
    int idx = blockIdx.x * blockDim.x + threadIdx.x;
    if (idx < 768 * CC) {
        int n = idx >> 8, k = idx & 255;
        const float* src = (n < 256) ? qw : (n < 512) ? kw : vw;
        g_hqkv[idx] = __float2half(src[k * CC + (n & 255)]);
    }
    if (idx < CC * CC) {
        int n = idx >> 8, k = idx & 255;
        g_hp[idx] = __float2half(pw[k * CC + n]);
    }
    if (idx < HH2 * 768) {
        int h = idx / 768, kk = idx % 768;
        int j = kk >> 8, c = kk & 255;
        g_hw1[idx] = __float2half(w1[h * 768 + c * 3 + j]);
    }
    if (idx < CC * HH2) g_hw2[idx] = __float2half(w2[idx]);
    if (idx < MM * CC) {
        int n = idx >> 8, k = idx & 255;
        g_hf1[idx] = __float2half(f1[k * MM + n]);
    }
    if (idx < CC * MM) {
        int n = idx >> 10, k = idx & 1023;
        g_hf2[idx] = __float2half(f2[k * CC + n]);
    }
    if (idx < EE * EE) g_maskf[idx] = 0.5f * (float)mask[idx];
    if (idx < HH2) {
        float s = b1w[idx] * rsqrtf(b1v[idx] + LNEPS);
        g_bn1s[idx] = s;
        g_bn1b[idx] = b1b[idx] - b1m[idx] * s;
    }
    if (idx < CC) {
        float s = b2w[idx] * rsqrtf(b2v[idx] + LNEPS);
        g_bn2s[idx] = s;
        g_bn2b[idx] = b2b[idx] - b2m[idx] * s;
    }
}

// ---------------- row reduce (mean, rstd) ----------------
__device__ __forceinline__ void row_stats(float v, int tid, float& mean, float& rstd)
{
    __shared__ float sa[8], sb[8];
    __syncthreads();
    float s = v, s2 = v * v;
    #pragma unroll
    for (int o = 16; o; o >>= 1) {
        s  += __shfl_down_sync(0xffffffffu, s,  o);
        s2 += __shfl_down_sync(0xffffffffu, s2, o);
    }
    int lane = tid & 31, wid = tid >> 5;
    if (!lane) { sa[wid] = s; sb[wid] = s2; }
    __syncthreads();
    if (tid < 32) {
        s  = (tid < 8) ? sa[tid] : 0.f;
        s2 = (tid < 8) ? sb[tid] : 0.f;
        #pragma unroll
        for (int o = 4; o; o >>= 1) {
            s  += __shfl_down_sync(0xffffffffu, s,  o);
            s2 += __shfl_down_sync(0xffffffffu, s2, o);
        }
        if (!tid) {
            float m = s * (1.f / CC);
            sa[0] = m;
            sb[0] = rsqrtf(s2 * (1.f / CC) - m * m + LNEPS);
        }
    }
    __syncthreads();
    mean = sa[0]; rstd = sb[0];
}

__global__ void ln_h_kernel(const float* __restrict__ in, const float* __restrict__ w,
                            const float* __restrict__ b, __half* __restrict__ o16)
{
    int tid = threadIdx.x;
    size_t idx = (size_t)blockIdx.x * CC + tid;
    float v = in[idx];
    float mean, rstd;
    row_stats(v, tid, mean, rstd);
    o16[idx] = __float2half((v - mean) * rstd * w[tid] + b[tid]);
}

// fused: x1 = x + xs + gamma_s*LN(P); xt16 = LN(x1)    (xs read as fp16)
__global__ void lnres_ln_kernel(const float* __restrict__ P, const float* __restrict__ x,
                                const __half* __restrict__ xs16, const float* __restrict__ ow,
                                const float* __restrict__ ob, const float* __restrict__ gamma,
                                const float* __restrict__ tw, const float* __restrict__ tb,
                                float* __restrict__ x1, __half* __restrict__ xt16)
{
    int tid = threadIdx.x;
    size_t idx = (size_t)blockIdx.x * CC + tid;
    float v = P[idx];
    float mean, rstd;
    row_stats(v, tid, mean, rstd);
    float ln = (v - mean) * rstd * ow[tid] + ob[tid];
    float xv = x[idx] + __half2float(xs16[idx]) + gamma[0] * ln;
    x1[idx] = xv;
    float mean2, rstd2;
    row_stats(xv, tid, mean2, rstd2);
    xt16[idx] = __float2half((xv - mean2) * rstd2 * tw[tid] + tb[tid]);
}

// ---------------- tensor-core attention (unchanged, verified) ------------------
#define MSTR 136
#define QSTR 40
#define VSTR 136
static constexpr int ATT_SMEM = 64000;

__global__ void __launch_bounds__(256, 2) attn_mma(const __half* __restrict__ QKV,
                                                   __half* __restrict__ O)
{
    extern __shared__ __align__(128) __half sm[];
    __half* maskS = sm;
    __half* Qs = sm + 17408;
    __half* Ks = Qs + 5120;
    __half* Vt = Ks + 5120;
    const int tid = threadIdx.x, w = tid >> 5, lane = tid & 31;
    const int bt = blockIdx.x;
    const int r = lane >> 2, c = lane & 3;
    const int eBase = w * 16;

    for (int i = tid; i < 128 * 32; i += 256) {
        int e = i >> 5, f4 = (i & 31) * 4;
        float4 mv = *(const float4*)&g_maskf[e * 128 + f4];
        __half2 h0 = __floats2half2_rn(mv.x, mv.y);
        __half2 h1 = __floats2half2_rn(mv.z, mv.w);
        *(uint2*)&maskS[e * MSTR + f4] = make_uint2(*(uint32_t*)&h0, *(uint32_t*)&h1);
    }
    __syncthreads();

    const __half* qbase = QKV + (size_t)bt * 128 * 768;
    const int se = tid >> 1, sp = tid & 1;

    for (int h = 0; h < 8; h++) {
        {
            const __half* row = qbase + (size_t)se * 768 + h * 32 + sp * 16;
            uint4 q0 = *(const uint4*)(row);
            uint4 q1 = *(const uint4*)(row + 8);
            *(uint4*)&Qs[se * QSTR + sp * 16]     = q0;
            *(uint4*)&Qs[se * QSTR + sp * 16 + 8] = q1;
            uint4 k0 = *(const uint4*)(row + 256);
            uint4 k1 = *(const uint4*)(row + 264);
            *(uint4*)&Ks[se * QSTR + sp * 16]     = k0;
            *(uint4*)&Ks[se * QSTR + sp * 16 + 8] = k1;
            uint4 v0 = *(const uint4*)(row + 512);
            uint4 v1 = *(const uint4*)(row + 520);
            const __half* vh0 = (const __half*)&v0;
            const __half* vh1 = (const __half*)&v1;
            #pragma unroll
            for (int i = 0; i < 8; i++) {
                Vt[(sp * 16 + i) * VSTR + se]     = vh0[i];
                Vt[(sp * 16 + 8 + i) * VSTR + se] = vh1[i];
            }
        }
        __syncthreads();

        uint4 aQ[2];
        #pragma unroll
        for (int ks = 0; ks < 2; ks++) {
            const __half* q0 = &Qs[(eBase + r) * QSTR + ks * 16 + 2 * c];
            aQ[ks].x = *(const uint32_t*)q0;
            aQ[ks].y = *(const uint32_t*)(q0 + 8 * QSTR);
            aQ[ks].z = *(const uint32_t*)(q0 + 8);
            aQ[ks].w = *(const uint32_t*)(q0 + 8 * QSTR + 8);
        }

        float oacc[4][4] = {};
        #pragma unroll
        for (int ph = 0; ph < 2; ph++) {
            float sacc[8][4] = {};
            #pragma unroll
            for (int nt = 0; nt < 8; nt++) {
                const __half* kp = &Ks[(ph * 64 + nt * 8 + r) * QSTR + 2 * c];
                #pragma unroll
                for (int ks = 0; ks < 2; ks++) {
                    uint2 bf;
                    bf.x = *(const uint32_t*)(kp + ks * 16);
                    bf.y = *(const uint32_t*)(kp + ks * 16 + 8);
                    mma16(sacc[nt], aQ[ks], bf);
                }
            }
            uint32_t wh[8][2];
            #pragma unroll
            for (int nt = 0; nt < 8; nt++) {
                int fb = ph * 64 + nt * 8 + 2 * c;
                float2 m0 = __half22float2(*(__half2*)&maskS[(eBase + r) * MSTR + fb]);
                float2 m1 = __half22float2(*(__half2*)&maskS[(eBase + r + 8) * MSTR + fb]);
                __half2 w0 = __floats2half2_rn(sacc[nt][0] * m0.x + 0.5f,
                                               sacc[nt][1] * m0.y + 0.5f);
                __half2 w1 = __floats2half2_rn(sacc[nt][2] * m1.x + 0.5f,
                                               sacc[nt][3] * m1.y + 0.5f);
                wh[nt][0] = *(uint32_t*)&w0;
                wh[nt][1] = *(uint32_t*)&w1;
            }
            #pragma unroll
            for (int kk = 0; kk < 4; kk++) {
                uint4 aw = make_uint4(wh[2 * kk][0], wh[2 * kk][1],
                                      wh[2 * kk + 1][0], wh[2 * kk + 1][1]);
                #pragma unroll
                for (int dt = 0; dt < 4; dt++) {
                    const __half* vp = &Vt[(dt * 8 + r) * VSTR + ph * 64 + kk * 16 + 2 * c];
                    uint2 bf;
                    bf.x = *(const uint32_t*)vp;
                    bf.y = *(const uint32_t*)(vp + 8);
                    mma16(oacc[dt], aw, bf);
                }
            }
        }
        size_t ob = ((size_t)bt * 128 + eBase + r) * 256 + h * 32;
        #pragma unroll
        for (int dt = 0; dt < 4; dt++) {
            __half2 o0 = __floats2half2_rn(oacc[dt][0], oacc[dt][1]);
            __half2 o1 = __floats2half2_rn(oacc[dt][2], oacc[dt][3]);
            *(uint32_t*)&O[ob + dt * 8 + 2 * c]           = *(uint32_t*)&o0;
            *(uint32_t*)&O[ob + 8 * 256 + dt * 8 + 2 * c] = *(uint32_t*)&o1;
        }
        __syncthreads();
    }
}

// ---------------- fp16 GEMM v2: cp.async + ldmatrix, 4-stage, 128x128, 256 thr --
// smem per stage: A [128 rows][64B] 8KB + B [128 rows][64B] 8KB. 4 stages = 64KB.
// chunk swizzle: c' = c ^ ((row>>1)&3)  (conflict-free ldmatrix + 16B cp.async)
static constexpr int HG_SMEM = 65536;

template<int KDIM, bool GATHER, bool OUTH>
__global__ void __launch_bounds__(256, 2) h_gemm(
        const __half* __restrict__ A, const __half* __restrict__ Bt,
        void* __restrict__ Cv, int N,
        const float* __restrict__ colScale, const float* __restrict__ colShift,
        int doGelu, const float* __restrict__ res, float resCoef,
        const float* __restrict__ vMul)
{
    extern __shared__ __align__(128) char smem[];
    constexpr int NT = KDIM / 32;
    const int tid = threadIdx.x;
    const int w = tid >> 5, lane = tid & 31;
    const int n0 = blockIdx.x * 128, m0 = blockIdx.y * 128;
    const int mg = w >> 2, ng = w & 3;
    const uint32_t sbase = smem_u32(smem);

    float acc[4][4][4] = {};

    auto produce = [&](int stg, int kt) {
        uint32_t sb = sbase + stg * 16384;
        #pragma unroll
        for (int it = 0; it < 2; it++) {
            int id = tid + it * 256;
            int row = id >> 2, c = id & 3;
            uint32_t swoff = (uint32_t)((c ^ ((row >> 1) & 3)) * 16);
            uint32_t dstA = sb + row * 64 + swoff;
            if (GATHER) {
                int kg = kt * 32 + c * 8;
                int j = kg >> 8, cc = kg & 255;
                int t = ((m0 + row) >> 7) & 63;
                int tt = t + j - 1;
                bool valid = (unsigned)tt < 64u;
                const __half* src = A + ((size_t)(m0 + row) + (ptrdiff_t)(j - 1) * EE) * CC + cc;
                cpa16z(dstA, valid ? src : (const __half*)A, valid ? 16 : 0);
            } else {
                cpa16(dstA, A + (size_t)(m0 + row) * KDIM + kt * 32 + c * 8);
            }
            cpa16(sb + 8192 + row * 64 + swoff,
                  Bt + (size_t)(n0 + row) * KDIM + kt * 32 + c * 8);
        }
    };
    auto compute = [&](int stg) {
        uint32_t sb = sbase + stg * 16384;
        #pragma unroll
        for (int ks = 0; ks < 2; ks++) {
            uint4 af[4];
            uint2 bf[4];
            #pragma unroll
            for (int mi = 0; mi < 4; mi++) {
                int row = mg * 64 + mi * 16 + (lane & 15);
                int ch = (ks * 2 + (lane >> 4)) ^ ((row >> 1) & 3);
                af[mi] = ldsm4(sb + row * 64 + ch * 16);
            }
            #pragma unroll
            for (int ni = 0; ni < 4; ni++) {
                int row = ng * 32 + ni * 8 + (lane & 7);
                int ch = (ks * 2 + ((lane >> 3) & 1)) ^ ((row >> 1) & 3);
                bf[ni] = ldsm2(sb + 8192 + row * 64 + ch * 16);
            }
            #pragma unroll
            for (int mi = 0; mi < 4; mi++)
                #pragma unroll
                for (int ni = 0; ni < 4; ni++)
                    mma16(acc[mi][ni], af[mi], bf[ni]);
        }
    };

    // prologue: fill 3 stages
    #pragma unroll
    for (int s = 0; s < 3; s++) {
        if (s < NT) produce(s, s);
        CP_COMMIT();
    }
    #pragma unroll 1
    for (int kt = 0; kt < NT; kt++) {
        CP_WAIT2();
        __syncthreads();
        if (kt + 3 < NT) produce((kt + 3) & 3, kt + 3);
        CP_COMMIT();
        compute(kt & 3);
    }

    // ---- epilogue ----
    const float vm = vMul ? *vMul : 1.0f;
    #pragma unroll
    for (int mi = 0; mi < 4; mi++) {
        #pragma unroll
        for (int ni = 0; ni < 4; ni++) {
            int r0 = m0 + (mg * 4 + mi) * 16 + (lane >> 2);
            int c0 = n0 + (ng * 4 + ni) * 8 + 2 * (lane & 3);
            #pragma unroll
            for (int half = 0; half < 2; half++) {
                int row = r0 + half * 8;
                float v0 = acc[mi][ni][half * 2 + 0];
                float v1 = acc[mi][ni][half * 2 + 1];
                size_t base = (size_t)row * N + c0;
                if (colScale) {
                    v0 = v0 * colScale[c0] + colShift[c0];
                    v1 = v1 * colScale[c0 + 1] + colShift[c0 + 1];
                } else if (colShift) {
                    v0 += colShift[c0];
                    v1 += colShift[c0 + 1];
                }
                if (doGelu) { v0 = gelu_exact(v0); v1 = gelu_exact(v1); }
                if (res) {
                    float2 r2 = *(const float2*)(res + base);
                    v0 = resCoef * r2.x + vm * v0;
                    v1 = resCoef * r2.y + vm * v1;
                }
                if (OUTH) {
                    __half2 h2v = __floats2half2_rn(v0, v1);
                    *(__half2*)((__half*)Cv + base) = h2v;
                } else {
                    *(float2*)((float*)Cv + base) = make_float2(v0, v1);
                }
            }
        }
    }
}

// NOTE on epilogue row mapping: warp's m-tiles are (mg*4+mi)*16 = mg*64 + mi*16,
// matching the ldmatrix A rows above.

// -------------------------------- launcher --------------------------------
template<typename T>
static T* symaddr(const void* sym)
{
    void* p = nullptr;
    cudaGetSymbolAddress(&p, sym);
    return (T*)p;
}

extern "C" void kernel_launch(void* const* d_in, const int* in_sizes, int n_in,
                              void* d_out, int out_size)
{
    const float* x       = (const float*)d_in[0];
    const int*   adj     = (const int*)  d_in[1];
    const float* n1_w    = (const float*)d_in[2];
    const float* n1_b    = (const float*)d_in[3];
    const float* q_w     = (const float*)d_in[4];
    const float* k_w     = (const float*)d_in[5];
    const float* v_w     = (const float*)d_in[6];
    const float* proj_w  = (const float*)d_in[7];
    const float* proj_b  = (const float*)d_in[8];
    const float* on_w    = (const float*)d_in[9];
    const float* on_b    = (const float*)d_in[10];
    const float* gamma_s = (const float*)d_in[11];
    const float* conv1_w = (const float*)d_in[12];
    const float* bn1_w   = (const float*)d_in[13];
    const float* bn1_b   = (const float*)d_in[14];
    const float* bn1_m   = (const float*)d_in[15];
    const float* bn1_v   = (const float*)d_in[16];
    const float* conv2_w = (const float*)d_in[17];
    const float* bn2_w   = (const float*)d_in[18];
    const float* bn2_b   = (const float*)d_in[19];
    const float* bn2_m   = (const float*)d_in[20];
    const float* bn2_v   = (const float*)d_in[21];
    const float* tn_w    = (const float*)d_in[22];
    const float* tn_b    = (const float*)d_in[23];
    const float* gamma_t = (const float*)d_in[24];
    const float* n3_w    = (const float*)d_in[25];
    const float* n3_b    = (const float*)d_in[26];
    const float* fc1_w   = (const float*)d_in[27];
    const float* fc1_b   = (const float*)d_in[28];
    const float* fc2_w   = (const float*)d_in[29];
    const float* fc2_b   = (const float*)d_in[30];
    float* out = (float*)d_out;

    __half* xs16 = symaddr<__half>(g_xs16);
    __half* qkvh = symaddr<__half>(g_qkvh);
    __half* o16  = symaddr<__half>(g_o16);
    float*  p    = symaddr<float >(g_p);
    float*  x1   = symaddr<float >(g_x1);
    __half* xt16 = symaddr<__half>(g_xt16);
    __half* y1h  = symaddr<__half>(g_y1h);
    float*  x2   = symaddr<float >(g_x2);
    __half* xm16 = symaddr<__half>(g_xm16);
    __half* bigh = symaddr<__half>(g_bigh);
    __half* hqkv = symaddr<__half>(g_hqkv);
    __half* hp   = symaddr<__half>(g_hp);
    __half* hw1  = symaddr<__half>(g_hw1);
    __half* hw2  = symaddr<__half>(g_hw2);
    __half* hf1  = symaddr<__half>(g_hf1);
    __half* hf2  = symaddr<__half>(g_hf2);
    float* bn1s = symaddr<float>(g_bn1s);
    float* bn1b = symaddr<float>(g_bn1b);
    float* bn2s = symaddr<float>(g_bn2s);
    float* bn2b = symaddr<float>(g_bn2b);

    cudaFuncSetAttribute(h_gemm<256,  false, true >, cudaFuncAttributeMaxDynamicSharedMemorySize, HG_SMEM);
    cudaFuncSetAttribute(h_gemm<256,  false, false>, cudaFuncAttributeMaxDynamicSharedMemorySize, HG_SMEM);
    cudaFuncSetAttribute(h_gemm<768,  true,  true >, cudaFuncAttributeMaxDynamicSharedMemorySize, HG_SMEM);
    cudaFuncSetAttribute(h_gemm<512,  false, false>, cudaFuncAttributeMaxDynamicSharedMemorySize, HG_SMEM);
    cudaFuncSetAttribute(h_gemm<1024, false, false>, cudaFuncAttributeMaxDynamicSharedMemorySize, HG_SMEM);
    cudaFuncSetAttribute(attn_mma, cudaFuncAttributeMaxDynamicSharedMemorySize, ATT_SMEM);

    // 0) prep
    prep_kernel<<<1536, 256>>>(q_w, k_w, v_w, proj_w, conv1_w, conv2_w, fc1_w, fc2_w, adj,
                               bn1_w, bn1_b, bn1_m, bn1_v,
                               bn2_w, bn2_b, bn2_m, bn2_v);

    // 1) xs = LN(x)  fp16
    ln_h_kernel<<<RROWS, 256>>>(x, n1_w, n1_b, xs16);

    // 2) fused QKV GEMM -> [R][768] fp16
    h_gemm<256, false, true><<<dim3(6, 512), 256, HG_SMEM>>>(xs16, hqkv, qkvh, 768,
        nullptr, nullptr, 0, nullptr, 0.f, nullptr);

    // 3) tensor-core masked attention -> o16
    attn_mma<<<BB * TT, 256, ATT_SMEM>>>(qkvh, o16);

    // 4) proj: P = o @ proj_w + proj_b
    h_gemm<256, false, false><<<dim3(2, 512), 256, HG_SMEM>>>(o16, hp, p, CC,
        nullptr, proj_b, 0, nullptr, 0.f, nullptr);

    // 5+6) x1 = x + xs + gamma_s*LN(P);  xt16 = LN(x1)
    lnres_ln_kernel<<<RROWS, 256>>>(p, x, xs16, on_w, on_b, gamma_s, tn_w, tn_b, x1, xt16);

    // 7) conv1 (gathered) + BN1 + GELU -> y1 fp16
    h_gemm<768, true, true><<<dim3(4, 512), 256, HG_SMEM>>>(xt16, hw1, y1h, HH2,
        bn1s, bn1b, 1, nullptr, 0.f, nullptr);

    // 8) conv2 + BN2, x2 = 2*x1 + gamma_t*y
    h_gemm<512, false, false><<<dim3(2, 512), 256, HG_SMEM>>>(y1h, hw2, x2, CC,
        bn2s, bn2b, 0, x1, 2.0f, gamma_t);

    // 9) xm = LN(x2) fp16
    ln_h_kernel<<<RROWS, 256>>>(x2, n3_w, n3_b, xm16);

    // 10) fc1 + bias + GELU -> big fp16
    h_gemm<256, false, true><<<dim3(8, 512), 256, HG_SMEM>>>(xm16, hf1, bigh, MM,
        nullptr, fc1_b, 1, nullptr, 0.f, nullptr);

    // 11) fc2 + bias + residual x2 -> out fp32
    h_gemm<1024, false, false><<<dim3(2, 512), 256, HG_SMEM>>>(bigh, hf2, out, CC,
        nullptr, fc2_b, 0, x2, 1.0f, nullptr);
}